// round 7
// baseline (speedup 1.0000x reference)
#include <cuda_runtime.h>
#include <cuda_bf16.h>
#include <cstdint>

#define B_  16
#define N_  1024
#define O_  64
#define H_  1024
#define D_  256

#define MV  (B_ * N_)      // 16384
#define MP  (B_ * O_)      // 1024

#define LOG_OFF  0
#define ATT_OFF  (B_ * O_)
#define EV_OFF   (ATT_OFF + B_ * O_ * N_)
#define LOSS_OFF (EV_OFF + B_ * O_ * D_)

// ---------------- device scratch ----------------
__device__ float g_visual[MV * D_];   // normalized visual (GEMM epilogue)
__device__ float g_phrase[MP * D_];   // normalized phrase (GEMM epilogue)
__device__ float g_protoN[MP * D_];   // normalized prototypes (GEMM epilogue)
__device__ float g_accum[2];

__device__ __align__(16) __nv_bfloat16 g_a_hi[MV * H_];
__device__ __align__(16) __nv_bfloat16 g_a_lo[MV * H_];
__device__ __align__(16) __nv_bfloat16 g_pa_hi[MP * H_];
__device__ __align__(16) __nv_bfloat16 g_pa_lo[MP * H_];
__device__ __align__(16) __nv_bfloat16 g_wv_hi[H_ * D_];   // row-major [K][N]
__device__ __align__(16) __nv_bfloat16 g_wv_lo[H_ * D_];
__device__ __align__(16) __nv_bfloat16 g_wp_hi[H_ * D_];
__device__ __align__(16) __nv_bfloat16 g_wp_lo[H_ * D_];

__global__ void k_zero() { g_accum[0] = 0.0f; g_accum[1] = 0.0f; }

// ---------------- helpers ----------------
__device__ __forceinline__ uint32_t smem_u32(const void* p) {
    uint32_t a;
    asm("{ .reg .u64 t; cvta.to.shared.u64 t, %1; cvt.u32.u64 %0, t; }" : "=r"(a) : "l"(p));
    return a;
}
__device__ __forceinline__ void cpa16(uint32_t s, const void* g) {
    asm volatile("cp.async.cg.shared.global [%0], [%1], 16;" :: "r"(s), "l"(g));
}
#define CP_COMMIT() asm volatile("cp.async.commit_group;" ::: "memory")
#define CP_WAIT1()  asm volatile("cp.async.wait_group 1;" ::: "memory")

__device__ __forceinline__ void ldm_x4(uint32_t* r, uint32_t a) {
    asm volatile("ldmatrix.sync.aligned.m8n8.x4.shared.b16 {%0,%1,%2,%3}, [%4];"
        : "=r"(r[0]), "=r"(r[1]), "=r"(r[2]), "=r"(r[3]) : "r"(a));
}
__device__ __forceinline__ void ldm_x4t(uint32_t* r, uint32_t a) {
    asm volatile("ldmatrix.sync.aligned.m8n8.x4.trans.shared.b16 {%0,%1,%2,%3}, [%4];"
        : "=r"(r[0]), "=r"(r[1]), "=r"(r[2]), "=r"(r[3]) : "r"(a));
}
__device__ __forceinline__ void mma16816(float* c, const uint32_t* a, const uint32_t* b) {
    asm volatile(
        "mma.sync.aligned.m16n8k16.row.col.f32.bf16.bf16.f32 "
        "{%0,%1,%2,%3}, {%4,%5,%6,%7}, {%8,%9}, {%0,%1,%2,%3};"
        : "+f"(c[0]), "+f"(c[1]), "+f"(c[2]), "+f"(c[3])
        : "r"(a[0]), "r"(a[1]), "r"(a[2]), "r"(a[3]), "r"(b[0]), "r"(b[1]));
}

__device__ __forceinline__ float warp_sum(float v) {
    #pragma unroll
    for (int o = 16; o > 0; o >>= 1) v += __shfl_xor_sync(0xffffffffu, v, o);
    return v;
}
__device__ __forceinline__ float warp_max(float v) {
    #pragma unroll
    for (int o = 16; o > 0; o >>= 1) v = fmaxf(v, __shfl_xor_sync(0xffffffffu, v, o));
    return v;
}

// ---------------- split conversion ----------------
__device__ __forceinline__ void split_one(const float* __restrict__ x,
                                          __nv_bfloat16* __restrict__ hi,
                                          __nv_bfloat16* __restrict__ lo, int i)
{
    float4 v = ((const float4*)x)[i];
    __nv_bfloat16 h0 = __float2bfloat16(v.x), h1 = __float2bfloat16(v.y);
    __nv_bfloat16 h2 = __float2bfloat16(v.z), h3 = __float2bfloat16(v.w);
    __nv_bfloat162 H0; H0.x = h0; H0.y = h1;
    __nv_bfloat162 H1; H1.x = h2; H1.y = h3;
    ((__nv_bfloat162*)hi)[i * 2]     = H0;
    ((__nv_bfloat162*)hi)[i * 2 + 1] = H1;
    __nv_bfloat162 L0, L1;
    L0.x = __float2bfloat16(v.x - __bfloat162float(h0));
    L0.y = __float2bfloat16(v.y - __bfloat162float(h1));
    L1.x = __float2bfloat16(v.z - __bfloat162float(h2));
    L1.y = __float2bfloat16(v.w - __bfloat162float(h3));
    ((__nv_bfloat162*)lo)[i * 2]     = L0;
    ((__nv_bfloat162*)lo)[i * 2 + 1] = L1;
}

__global__ __launch_bounds__(256) void k_split(const float* __restrict__ x,
                                               __nv_bfloat16* __restrict__ hi,
                                               __nv_bfloat16* __restrict__ lo, int n4)
{
    for (int i = blockIdx.x * blockDim.x + threadIdx.x; i < n4; i += gridDim.x * blockDim.x)
        split_one(x, hi, lo, i);
}

// both weight matrices in one launch
__global__ __launch_bounds__(256) void k_split_w(const float* __restrict__ Wv,
                                                 const float* __restrict__ Wp)
{
    const int n4 = H_ * D_ / 4;
    for (int i = blockIdx.x * blockDim.x + threadIdx.x; i < 2 * n4; i += gridDim.x * blockDim.x) {
        if (i < n4) split_one(Wv, g_wv_hi, g_wv_lo, i);
        else        split_one(Wp, g_wp_hi, g_wp_lo, i - n4);
    }
}

// ---------------- mma.sync GEMM, BM=64 BN=256(full D) BK=32, 2 CTA/SM --------
// 256 threads = 8 warps (2m x 4n), warp tile 32x64.
// Epilogue: bias + fused row L2-normalize; phrase CTAs also build protoN.
#define NSTAGE (H_ / 32)
#define ST_AH 0
#define ST_AL 4096
#define ST_BH 8192
#define ST_BL 24576
#define SMEM_STAGE 40960
#define GEMM_SMEM (2 * SMEM_STAGE)

__global__ __launch_bounds__(256, 2) void k_gemm_mma(const float* __restrict__ bv,
                                                     const float* __restrict__ bp,
                                                     const float* __restrict__ proto)
{
    extern __shared__ char smem[];
    const uint32_t sb = smem_u32(smem);
    const int tid = threadIdx.x;
    const int lane = tid & 31;
    const int wid = tid >> 5;          // 0..7
    const int wm = wid & 1;            // 0..1
    const int wn = wid >> 1;           // 0..3

    const bool isV = blockIdx.x < (MV / 64);
    const __nv_bfloat16 *Ah, *Al, *Bh, *Bl;
    const float* bias;
    float* C;
    int m0;
    if (isV) { Ah = g_a_hi;  Al = g_a_lo;  Bh = g_wv_hi; Bl = g_wv_lo; bias = bv; C = g_visual; m0 = blockIdx.x * 64; }
    else     { Ah = g_pa_hi; Al = g_pa_lo; Bh = g_wp_hi; Bl = g_wp_lo; bias = bp; C = g_phrase; m0 = (blockIdx.x - MV / 64) * 64; }

    // load coords: A = 64 rows x 4 chunks (16B); B = 32 rows x 32 chunks (16B)
    const int a_r = tid >> 2;              // 0..63
    const int a_c = tid & 3;
    const uint32_t a_so = (uint32_t)(a_r * 64 + ((a_c ^ ((a_r >> 1) & 3)) << 4));
    const int b_r = tid >> 3;              // 0..31
    const int b_c = tid & 7;               // base chunk; +8,+16,+24 also loaded

    uint32_t b_so[4];
    #pragma unroll
    for (int q = 0; q < 4; q++)
        b_so[q] = (uint32_t)(b_r * 512 + (((b_c + q * 8) ^ (b_r & 7)) << 4));

    float acc[2][8][4];
    #pragma unroll
    for (int i = 0; i < 2; i++)
        #pragma unroll
        for (int j = 0; j < 8; j++)
            #pragma unroll
            for (int k = 0; k < 4; k++) acc[i][j][k] = 0.0f;

    // prologue (stage 0)
    {
        const uint32_t st = sb;
        cpa16(st + ST_AH + a_so, Ah + (size_t)(m0 + a_r) * H_ + a_c * 8);
        cpa16(st + ST_AL + a_so, Al + (size_t)(m0 + a_r) * H_ + a_c * 8);
        #pragma unroll
        for (int q = 0; q < 4; q++) {
            cpa16(st + ST_BH + b_so[q], Bh + (size_t)b_r * D_ + (b_c + q * 8) * 8);
            cpa16(st + ST_BL + b_so[q], Bl + (size_t)b_r * D_ + (b_c + q * 8) * 8);
        }
    }
    CP_COMMIT();

    for (int s = 0; s < NSTAGE; s++) {
        if (s + 1 < NSTAGE) {
            const int k0 = (s + 1) * 32;
            const uint32_t st = sb + ((s + 1) & 1) * SMEM_STAGE;
            cpa16(st + ST_AH + a_so, Ah + (size_t)(m0 + a_r) * H_ + k0 + a_c * 8);
            cpa16(st + ST_AL + a_so, Al + (size_t)(m0 + a_r) * H_ + k0 + a_c * 8);
            #pragma unroll
            for (int q = 0; q < 4; q++) {
                cpa16(st + ST_BH + b_so[q], Bh + (size_t)(k0 + b_r) * D_ + (b_c + q * 8) * 8);
                cpa16(st + ST_BL + b_so[q], Bl + (size_t)(k0 + b_r) * D_ + (b_c + q * 8) * 8);
            }
        }
        CP_COMMIT();
        CP_WAIT1();
        __syncthreads();

        const uint32_t base = sb + (s & 1) * SMEM_STAGE;

        #pragma unroll
        for (int ks = 0; ks < 2; ks++) {
            uint32_t ahf[2][4], alf[2][4];
            #pragma unroll
            for (int mf = 0; mf < 2; mf++) {
                const int row = wm * 32 + mf * 16 + ((lane >> 3) & 1) * 8 + (lane & 7);
                const int ch  = ks * 2 + (lane >> 4);
                const uint32_t addr = base + ST_AH + (uint32_t)(row * 64 + ((ch ^ ((row >> 1) & 3)) << 4));
                ldm_x4(ahf[mf], addr);
                ldm_x4(alf[mf], addr + (ST_AL - ST_AH));
            }
            #pragma unroll
            for (int g = 0; g < 4; g++) {
                const int row = ks * 16 + ((lane >> 3) & 1) * 8 + (lane & 7);
                const int ch  = wn * 8 + g * 2 + (lane >> 4);
                const uint32_t addr = base + ST_BH + (uint32_t)(row * 512 + ((ch ^ (row & 7)) << 4));
                uint32_t th[4], tl[4];
                ldm_x4t(th, addr);
                ldm_x4t(tl, addr + (ST_BL - ST_BH));
                uint32_t bh0[2] = {th[0], th[1]}, bh1[2] = {th[2], th[3]};
                uint32_t bl0[2] = {tl[0], tl[1]}, bl1[2] = {tl[2], tl[3]};
                #pragma unroll
                for (int mf = 0; mf < 2; mf++) {
                    mma16816(acc[mf][g * 2],     ahf[mf], bh0);
                    mma16816(acc[mf][g * 2],     ahf[mf], bl0);
                    mma16816(acc[mf][g * 2],     alf[mf], bh0);
                    mma16816(acc[mf][g * 2 + 1], ahf[mf], bh1);
                    mma16816(acc[mf][g * 2 + 1], ahf[mf], bl1);
                    mma16816(acc[mf][g * 2 + 1], alf[mf], bh1);
                }
            }
        }
        __syncthreads();
    }

    // ---- epilogue: bias + fused L2 row-normalize + store ----
    #pragma unroll
    for (int mf = 0; mf < 2; mf++)
        #pragma unroll
        for (int nf = 0; nf < 8; nf++) {
            const int n = wn * 64 + nf * 8 + (lane & 3) * 2;
            const float bx = bias[n], by = bias[n + 1];
            acc[mf][nf][0] += bx; acc[mf][nf][1] += by;
            acc[mf][nf][2] += bx; acc[mf][nf][3] += by;
        }

    float* part = (float*)smem;   // [4][64] per-wn row partial sq-sums
    #pragma unroll
    for (int mf = 0; mf < 2; mf++) {
        float p0 = 0.0f, p1 = 0.0f;
        #pragma unroll
        for (int nf = 0; nf < 8; nf++) {
            p0 = fmaf(acc[mf][nf][0], acc[mf][nf][0], p0);
            p0 = fmaf(acc[mf][nf][1], acc[mf][nf][1], p0);
            p1 = fmaf(acc[mf][nf][2], acc[mf][nf][2], p1);
            p1 = fmaf(acc[mf][nf][3], acc[mf][nf][3], p1);
        }
        p0 += __shfl_xor_sync(0xffffffffu, p0, 1);
        p0 += __shfl_xor_sync(0xffffffffu, p0, 2);
        p1 += __shfl_xor_sync(0xffffffffu, p1, 1);
        p1 += __shfl_xor_sync(0xffffffffu, p1, 2);
        if ((lane & 3) == 0) {
            const int r = wm * 32 + mf * 16 + (lane >> 2);
            part[wn * 64 + r]     = p0;
            part[wn * 64 + r + 8] = p1;
        }
    }
    __syncthreads();

    #pragma unroll
    for (int mf = 0; mf < 2; mf++) {
        const int r0 = wm * 32 + mf * 16 + (lane >> 2);
        const int r1 = r0 + 8;
        const float s0 = part[r0] + part[64 + r0] + part[128 + r0] + part[192 + r0];
        const float s1 = part[r1] + part[64 + r1] + part[128 + r1] + part[192 + r1];
        const float inv0 = 1.0f / fmaxf(sqrtf(s0), 1e-12f);
        const float inv1 = 1.0f / fmaxf(sqrtf(s1), 1e-12f);
        #pragma unroll
        for (int nf = 0; nf < 8; nf++) {
            const int n = wn * 64 + nf * 8 + (lane & 3) * 2;
            acc[mf][nf][0] *= inv0; acc[mf][nf][1] *= inv0;
            acc[mf][nf][2] *= inv1; acc[mf][nf][3] *= inv1;
            float2 w0; w0.x = acc[mf][nf][0]; w0.y = acc[mf][nf][1];
            float2 w1; w1.x = acc[mf][nf][2]; w1.y = acc[mf][nf][3];
            *(float2*)&C[(size_t)(m0 + r0) * D_ + n] = w0;
            *(float2*)&C[(size_t)(m0 + r1) * D_ + n] = w1;
        }
    }

    // ---- phrase CTAs: prototypes = l2norm(proto + normalized phrase) ----
    if (!isV) {
        __syncthreads();   // part safe to reuse
        #pragma unroll
        for (int mf = 0; mf < 2; mf++) {
            const int r0l = wm * 32 + mf * 16 + (lane >> 2);   // local row = o index
            float p0 = 0.0f, p1 = 0.0f;
            #pragma unroll
            for (int nf = 0; nf < 8; nf++) {
                const int n = wn * 64 + nf * 8 + (lane & 3) * 2;
                const float2 pr0 = *(const float2*)&proto[(size_t)r0l * D_ + n];
                const float2 pr1 = *(const float2*)&proto[(size_t)(r0l + 8) * D_ + n];
                acc[mf][nf][0] += pr0.x; acc[mf][nf][1] += pr0.y;
                acc[mf][nf][2] += pr1.x; acc[mf][nf][3] += pr1.y;
                p0 = fmaf(acc[mf][nf][0], acc[mf][nf][0], p0);
                p0 = fmaf(acc[mf][nf][1], acc[mf][nf][1], p0);
                p1 = fmaf(acc[mf][nf][2], acc[mf][nf][2], p1);
                p1 = fmaf(acc[mf][nf][3], acc[mf][nf][3], p1);
            }
            p0 += __shfl_xor_sync(0xffffffffu, p0, 1);
            p0 += __shfl_xor_sync(0xffffffffu, p0, 2);
            p1 += __shfl_xor_sync(0xffffffffu, p1, 1);
            p1 += __shfl_xor_sync(0xffffffffu, p1, 2);
            if ((lane & 3) == 0) {
                const int r = wm * 32 + mf * 16 + (lane >> 2);
                part[wn * 64 + r]     = p0;
                part[wn * 64 + r + 8] = p1;
            }
        }
        __syncthreads();
        #pragma unroll
        for (int mf = 0; mf < 2; mf++) {
            const int r0 = wm * 32 + mf * 16 + (lane >> 2);
            const int r1 = r0 + 8;
            const float s0 = part[r0] + part[64 + r0] + part[128 + r0] + part[192 + r0];
            const float s1 = part[r1] + part[64 + r1] + part[128 + r1] + part[192 + r1];
            const float inv0 = 1.0f / fmaxf(sqrtf(s0), 1e-12f);
            const float inv1 = 1.0f / fmaxf(sqrtf(s1), 1e-12f);
            #pragma unroll
            for (int nf = 0; nf < 8; nf++) {
                const int n = wn * 64 + nf * 8 + (lane & 3) * 2;
                float2 w0; w0.x = acc[mf][nf][0] * inv0; w0.y = acc[mf][nf][1] * inv0;
                float2 w1; w1.x = acc[mf][nf][2] * inv1; w1.y = acc[mf][nf][3] * inv1;
                *(float2*)&g_protoN[(size_t)(m0 + r0) * D_ + n] = w0;
                *(float2*)&g_protoN[(size_t)(m0 + r1) * D_ + n] = w1;
            }
        }
    }
}

// ---------------- fused attention ----------------
__global__ __launch_bounds__(256) void k_attention(
    const float* __restrict__ labels, const float* __restrict__ Wc,
    const float* __restrict__ bcp, float* __restrict__ out)
{
    __shared__ float sp[8][D_];
    __shared__ float attn_s[8][N_];
    __shared__ float s_red[8];
    __shared__ float s_ent;

    const int tid = threadIdx.x;
    const int og = blockIdx.x;
    const int b  = blockIdx.y;
    const int wid = tid / 32, lane = tid % 32;
    const int row0 = b * O_ + og * 8;

    #pragma unroll
    for (int i = 0; i < 8; i++)
        sp[i][tid] = g_protoN[(size_t)(row0 + i) * D_ + tid];
    if (tid == 0) s_ent = 0.0f;
    __syncthreads();

    {
        const float* v0 = g_visual + ((size_t)(b * N_ + tid)) * D_;
        const float* v1 = v0 + 256 * D_;
        const float* v2 = v1 + 256 * D_;
        const float* v3 = v2 + 256 * D_;
        float acc[8][4];
        #pragma unroll
        for (int o = 0; o < 8; o++)
            #pragma unroll
            for (int i = 0; i < 4; i++) acc[o][i] = 0.0f;

        #pragma unroll 4
        for (int d = 0; d < D_; d++) {
            const float a = v0[d], b2 = v1[d], c = v2[d], e = v3[d];
            #pragma unroll
            for (int o = 0; o < 8; o++) {
                const float s = sp[o][d];
                acc[o][0] = fmaf(s, a,  acc[o][0]);
                acc[o][1] = fmaf(s, b2, acc[o][1]);
                acc[o][2] = fmaf(s, c,  acc[o][2]);
                acc[o][3] = fmaf(s, e,  acc[o][3]);
            }
        }
        #pragma unroll
        for (int o = 0; o < 8; o++)
            #pragma unroll
            for (int i = 0; i < 4; i++)
                attn_s[o][tid + 256 * i] = acc[o][i];
    }
    __syncthreads();

    {
        const int o = wid;
        float4 vals[8];
        #pragma unroll
        for (int j = 0; j < 8; j++)
            vals[j] = *(float4*)&attn_s[o][lane * 4 + 128 * j];
        float mx = -1e30f;
        #pragma unroll
        for (int j = 0; j < 8; j++)
            mx = fmaxf(mx, fmaxf(fmaxf(vals[j].x, vals[j].y), fmaxf(vals[j].z, vals[j].w)));
        mx = warp_max(mx);
        float sum = 0.0f;
        #pragma unroll
        for (int j = 0; j < 8; j++) {
            vals[j].x = expf(vals[j].x - mx);
            vals[j].y = expf(vals[j].y - mx);
            vals[j].z = expf(vals[j].z - mx);
            vals[j].w = expf(vals[j].w - mx);
            sum += vals[j].x + vals[j].y + vals[j].z + vals[j].w;
        }
        sum = warp_sum(sum);
        const float inv = 1.0f / sum;
        float ent = 0.0f;
        float* outA = out + ATT_OFF + (size_t)(row0 + o) * N_;
        #pragma unroll
        for (int j = 0; j < 8; j++) {
            vals[j].x *= inv; vals[j].y *= inv; vals[j].z *= inv; vals[j].w *= inv;
            *(float4*)&attn_s[o][lane * 4 + 128 * j] = vals[j];
            *(float4*)&outA[lane * 4 + 128 * j] = vals[j];
            ent += vals[j].x * logf(fmaxf(vals[j].x, 1e-8f));
            ent += vals[j].y * logf(fmaxf(vals[j].y, 1e-8f));
            ent += vals[j].z * logf(fmaxf(vals[j].z, 1e-8f));
            ent += vals[j].w * logf(fmaxf(vals[j].w, 1e-8f));
        }
        ent = warp_sum(ent);
        if (lane == 0) atomicAdd(&s_ent, ent);
    }
    __syncthreads();

    float ev[8];
    #pragma unroll
    for (int o = 0; o < 8; o++) ev[o] = 0.0f;
    {
        const float* vcol = g_visual + (size_t)b * N_ * D_ + tid;
        #pragma unroll 4
        for (int n = 0; n < N_; n++) {
            const float v = vcol[(size_t)n * D_];
            #pragma unroll
            for (int o = 0; o < 8; o++)
                ev[o] = fmaf(attn_s[o][n], v, ev[o]);
        }
    }

    #pragma unroll
    for (int o = 0; o < 8; o++)
        out[EV_OFF + (size_t)(row0 + o) * D_ + tid] = ev[o];

    const float lw = Wc[tid];
    const float bc = bcp[0];
    #pragma unroll
    for (int o = 0; o < 8; o++) {
        float v = warp_sum(ev[o] * lw);
        if (lane == 0) s_red[wid] = v;
        __syncthreads();
        if (tid == 0) {
            float s = 0.0f;
            #pragma unroll
            for (int w = 0; w < 8; w++) s += s_red[w];
            out[LOG_OFF + row0 + o] = s + bc;
        }
        __syncthreads();
    }

    float lsum = 0.0f;
    #pragma unroll
    for (int o = 0; o < 8; o++) {
        const int row = row0 + o;
        const float lab = labels[row];
        const float ph = g_phrase[(size_t)row * D_ + tid];
        const float df = ev[o] - lab * ph;
        lsum = fmaf(df, df, lsum);
    }
    lsum = warp_sum(lsum);
    if (lane == 0) s_red[wid] = lsum;
    __syncthreads();
    if (tid == 0) {
        float s = 0.0f;
        #pragma unroll
        for (int w = 0; w < 8; w++) s += s_red[w];
        atomicAdd(&g_accum[0], s);
        atomicAdd(&g_accum[1], s_ent);
    }
}

__global__ void k_finalize(float* __restrict__ out) {
    const float proto_loss = g_accum[0] / (float)(B_ * O_ * D_);
    const float sparse_loss = -g_accum[1] / (float)(B_ * O_);
    out[LOSS_OFF] = proto_loss + 0.01f * sparse_loss;
}

// ---------------- launch ----------------
extern "C" void kernel_launch(void* const* d_in, const int* in_sizes, int n_in,
                              void* d_out, int out_size)
{
    (void)in_sizes; (void)n_in; (void)out_size;
    const float* visual_tokens = (const float*)d_in[0];
    const float* phrase_states = (const float*)d_in[1];
    const float* labels        = (const float*)d_in[2];
    const float* Wv            = (const float*)d_in[3];
    const float* bv            = (const float*)d_in[4];
    const float* Wp            = (const float*)d_in[5];
    const float* bp            = (const float*)d_in[6];
    const float* proto         = (const float*)d_in[7];
    const float* Wc            = (const float*)d_in[8];
    const float* bc            = (const float*)d_in[9];
    float* out = (float*)d_out;

    __nv_bfloat16 *ah, *al, *pah, *pal;
    cudaGetSymbolAddress((void**)&ah,  g_a_hi);
    cudaGetSymbolAddress((void**)&al,  g_a_lo);
    cudaGetSymbolAddress((void**)&pah, g_pa_hi);
    cudaGetSymbolAddress((void**)&pal, g_pa_lo);

    cudaFuncSetAttribute(k_gemm_mma, cudaFuncAttributeMaxDynamicSharedMemorySize, GEMM_SMEM);

    k_zero<<<1, 1>>>();
    k_split<<<4096, 256>>>(visual_tokens, ah, al, MV * H_ / 4);
    k_split<<<1024, 256>>>(phrase_states, pah, pal, MP * H_ / 4);
    k_split_w<<<512, 256>>>(Wv, Wp);
    k_gemm_mma<<<MV / 64 + MP / 64, 256, GEMM_SMEM>>>(bv, bp, proto);
    k_attention<<<dim3(8, B_), 256>>>(labels, Wc, bc, out);
    k_finalize<<<1, 1>>>(out);
}

// round 9
// speedup vs baseline: 1.9249x; 1.9249x over previous
#include <cuda_runtime.h>
#include <cuda_bf16.h>
#include <cstdint>

#define B_  16
#define N_  1024
#define O_  64
#define H_  1024
#define D_  256

#define MV  (B_ * N_)      // 16384
#define MP  (B_ * O_)      // 1024

#define LOG_OFF  0
#define ATT_OFF  (B_ * O_)
#define EV_OFF   (ATT_OFF + B_ * O_ * N_)
#define LOSS_OFF (EV_OFF + B_ * O_ * D_)

// ---------------- device scratch ----------------
__device__ float g_phrase[MP * D_];   // normalized phrase fp32 (for loss)
__device__ float g_accum[2];

__device__ __align__(16) __nv_bfloat16 g_a_hi[MV * H_];
__device__ __align__(16) __nv_bfloat16 g_a_lo[MV * H_];
__device__ __align__(16) __nv_bfloat16 g_pa_hi[MP * H_];
__device__ __align__(16) __nv_bfloat16 g_pa_lo[MP * H_];
__device__ __align__(16) __nv_bfloat16 g_wv_hi[H_ * D_];
__device__ __align__(16) __nv_bfloat16 g_wv_lo[H_ * D_];
__device__ __align__(16) __nv_bfloat16 g_wp_hi[H_ * D_];
__device__ __align__(16) __nv_bfloat16 g_wp_lo[H_ * D_];

// normalized outputs in bf16 hi/lo (produced by GEMM epilogue)
__device__ __align__(16) __nv_bfloat16 g_vis_hi[MV * D_];
__device__ __align__(16) __nv_bfloat16 g_vis_lo[MV * D_];
__device__ __align__(16) __nv_bfloat16 g_proto_hi[MP * D_];
__device__ __align__(16) __nv_bfloat16 g_proto_lo[MP * D_];

__global__ void k_zero() { g_accum[0] = 0.0f; g_accum[1] = 0.0f; }

// ---------------- helpers ----------------
__device__ __forceinline__ uint32_t smem_u32(const void* p) {
    uint32_t a;
    asm("{ .reg .u64 t; cvta.to.shared.u64 t, %1; cvt.u32.u64 %0, t; }" : "=r"(a) : "l"(p));
    return a;
}
__device__ __forceinline__ void cpa16(uint32_t s, const void* g) {
    asm volatile("cp.async.cg.shared.global [%0], [%1], 16;" :: "r"(s), "l"(g));
}
#define CP_COMMIT() asm volatile("cp.async.commit_group;" ::: "memory")
#define CP_WAIT1()  asm volatile("cp.async.wait_group 1;" ::: "memory")
#define CP_WAIT0()  asm volatile("cp.async.wait_group 0;" ::: "memory")

__device__ __forceinline__ void ldm_x4(uint32_t* r, uint32_t a) {
    asm volatile("ldmatrix.sync.aligned.m8n8.x4.shared.b16 {%0,%1,%2,%3}, [%4];"
        : "=r"(r[0]), "=r"(r[1]), "=r"(r[2]), "=r"(r[3]) : "r"(a));
}
__device__ __forceinline__ void ldm_x2(uint32_t* r, uint32_t a) {
    asm volatile("ldmatrix.sync.aligned.m8n8.x2.shared.b16 {%0,%1}, [%2];"
        : "=r"(r[0]), "=r"(r[1]) : "r"(a));
}
__device__ __forceinline__ void ldm_x4t(uint32_t* r, uint32_t a) {
    asm volatile("ldmatrix.sync.aligned.m8n8.x4.trans.shared.b16 {%0,%1,%2,%3}, [%4];"
        : "=r"(r[0]), "=r"(r[1]), "=r"(r[2]), "=r"(r[3]) : "r"(a));
}
__device__ __forceinline__ void mma16816(float* c, const uint32_t* a, const uint32_t* b) {
    asm volatile(
        "mma.sync.aligned.m16n8k16.row.col.f32.bf16.bf16.f32 "
        "{%0,%1,%2,%3}, {%4,%5,%6,%7}, {%8,%9}, {%0,%1,%2,%3};"
        : "+f"(c[0]), "+f"(c[1]), "+f"(c[2]), "+f"(c[3])
        : "r"(a[0]), "r"(a[1]), "r"(a[2]), "r"(a[3]), "r"(b[0]), "r"(b[1]));
}

__device__ __forceinline__ float warp_sum(float v) {
    #pragma unroll
    for (int o = 16; o > 0; o >>= 1) v += __shfl_xor_sync(0xffffffffu, v, o);
    return v;
}
__device__ __forceinline__ float warp_max(float v) {
    #pragma unroll
    for (int o = 16; o > 0; o >>= 1) v = fmaxf(v, __shfl_xor_sync(0xffffffffu, v, o));
    return v;
}

__device__ __forceinline__ void split_pair(float x, float y, __nv_bfloat16* hi, __nv_bfloat16* lo) {
    __nv_bfloat162 h, l;
    h.x = __float2bfloat16(x); h.y = __float2bfloat16(y);
    l.x = __float2bfloat16(x - __bfloat162float(h.x));
    l.y = __float2bfloat16(y - __bfloat162float(h.y));
    *(__nv_bfloat162*)hi = h;
    *(__nv_bfloat162*)lo = l;
}

// ---------------- split conversion ----------------
__device__ __forceinline__ void split_one(const float* __restrict__ x,
                                          __nv_bfloat16* __restrict__ hi,
                                          __nv_bfloat16* __restrict__ lo, int i)
{
    float4 v = ((const float4*)x)[i];
    __nv_bfloat16 h0 = __float2bfloat16(v.x), h1 = __float2bfloat16(v.y);
    __nv_bfloat16 h2 = __float2bfloat16(v.z), h3 = __float2bfloat16(v.w);
    __nv_bfloat162 H0; H0.x = h0; H0.y = h1;
    __nv_bfloat162 H1; H1.x = h2; H1.y = h3;
    ((__nv_bfloat162*)hi)[i * 2]     = H0;
    ((__nv_bfloat162*)hi)[i * 2 + 1] = H1;
    __nv_bfloat162 L0, L1;
    L0.x = __float2bfloat16(v.x - __bfloat162float(h0));
    L0.y = __float2bfloat16(v.y - __bfloat162float(h1));
    L1.x = __float2bfloat16(v.z - __bfloat162float(h2));
    L1.y = __float2bfloat16(v.w - __bfloat162float(h3));
    ((__nv_bfloat162*)lo)[i * 2]     = L0;
    ((__nv_bfloat162*)lo)[i * 2 + 1] = L1;
}

__global__ __launch_bounds__(256) void k_split(const float* __restrict__ x,
                                               __nv_bfloat16* __restrict__ hi,
                                               __nv_bfloat16* __restrict__ lo, int n4)
{
    for (int i = blockIdx.x * blockDim.x + threadIdx.x; i < n4; i += gridDim.x * blockDim.x)
        split_one(x, hi, lo, i);
}

__global__ __launch_bounds__(256) void k_split_w(const float* __restrict__ Wv,
                                                 const float* __restrict__ Wp)
{
    const int n4 = H_ * D_ / 4;
    for (int i = blockIdx.x * blockDim.x + threadIdx.x; i < 2 * n4; i += gridDim.x * blockDim.x) {
        if (i < n4) split_one(Wv, g_wv_hi, g_wv_lo, i);
        else        split_one(Wp, g_wp_hi, g_wp_lo, i - n4);
    }
}

// ---------------- mma.sync GEMM, BM=64 BN=256 BK=32, 2 CTA/SM ----------------
#define NSTAGE (H_ / 32)
#define ST_AH 0
#define ST_AL 4096
#define ST_BH 8192
#define ST_BL 24576
#define SMEM_STAGE 40960
#define GEMM_SMEM (2 * SMEM_STAGE)

__global__ __launch_bounds__(256, 2) void k_gemm_mma(const float* __restrict__ bv,
                                                     const float* __restrict__ bp,
                                                     const float* __restrict__ proto)
{
    extern __shared__ char smem[];
    const uint32_t sb = smem_u32(smem);
    const int tid = threadIdx.x;
    const int lane = tid & 31;
    const int wid = tid >> 5;
    const int wm = wid & 1;
    const int wn = wid >> 1;

    const bool isV = blockIdx.x < (MV / 64);
    const __nv_bfloat16 *Ah, *Al, *Bh, *Bl;
    const float* bias;
    int m0;
    if (isV) { Ah = g_a_hi;  Al = g_a_lo;  Bh = g_wv_hi; Bl = g_wv_lo; bias = bv; m0 = blockIdx.x * 64; }
    else     { Ah = g_pa_hi; Al = g_pa_lo; Bh = g_wp_hi; Bl = g_wp_lo; bias = bp; m0 = (blockIdx.x - MV / 64) * 64; }

    const int a_r = tid >> 2;
    const int a_c = tid & 3;
    const uint32_t a_so = (uint32_t)(a_r * 64 + ((a_c ^ ((a_r >> 1) & 3)) << 4));
    const int b_r = tid >> 3;
    const int b_c = tid & 7;

    uint32_t b_so[4];
    #pragma unroll
    for (int q = 0; q < 4; q++)
        b_so[q] = (uint32_t)(b_r * 512 + (((b_c + q * 8) ^ (b_r & 7)) << 4));

    float acc[2][8][4];
    #pragma unroll
    for (int i = 0; i < 2; i++)
        #pragma unroll
        for (int j = 0; j < 8; j++)
            #pragma unroll
            for (int k = 0; k < 4; k++) acc[i][j][k] = 0.0f;

    {
        const uint32_t st = sb;
        cpa16(st + ST_AH + a_so, Ah + (size_t)(m0 + a_r) * H_ + a_c * 8);
        cpa16(st + ST_AL + a_so, Al + (size_t)(m0 + a_r) * H_ + a_c * 8);
        #pragma unroll
        for (int q = 0; q < 4; q++) {
            cpa16(st + ST_BH + b_so[q], Bh + (size_t)b_r * D_ + (b_c + q * 8) * 8);
            cpa16(st + ST_BL + b_so[q], Bl + (size_t)b_r * D_ + (b_c + q * 8) * 8);
        }
    }
    CP_COMMIT();

    for (int s = 0; s < NSTAGE; s++) {
        if (s + 1 < NSTAGE) {
            const int k0 = (s + 1) * 32;
            const uint32_t st = sb + ((s + 1) & 1) * SMEM_STAGE;
            cpa16(st + ST_AH + a_so, Ah + (size_t)(m0 + a_r) * H_ + k0 + a_c * 8);
            cpa16(st + ST_AL + a_so, Al + (size_t)(m0 + a_r) * H_ + k0 + a_c * 8);
            #pragma unroll
            for (int q = 0; q < 4; q++) {
                cpa16(st + ST_BH + b_so[q], Bh + (size_t)(k0 + b_r) * D_ + (b_c + q * 8) * 8);
                cpa16(st + ST_BL + b_so[q], Bl + (size_t)(k0 + b_r) * D_ + (b_c + q * 8) * 8);
            }
        }
        CP_COMMIT();
        CP_WAIT1();
        __syncthreads();

        const uint32_t base = sb + (s & 1) * SMEM_STAGE;

        #pragma unroll
        for (int ks = 0; ks < 2; ks++) {
            uint32_t ahf[2][4], alf[2][4];
            #pragma unroll
            for (int mf = 0; mf < 2; mf++) {
                const int row = wm * 32 + mf * 16 + ((lane >> 3) & 1) * 8 + (lane & 7);
                const int ch  = ks * 2 + (lane >> 4);
                const uint32_t addr = base + ST_AH + (uint32_t)(row * 64 + ((ch ^ ((row >> 1) & 3)) << 4));
                ldm_x4(ahf[mf], addr);
                ldm_x4(alf[mf], addr + (ST_AL - ST_AH));
            }
            #pragma unroll
            for (int g = 0; g < 4; g++) {
                const int row = ks * 16 + ((lane >> 3) & 1) * 8 + (lane & 7);
                const int ch  = wn * 8 + g * 2 + (lane >> 4);
                const uint32_t addr = base + ST_BH + (uint32_t)(row * 512 + ((ch ^ (row & 7)) << 4));
                uint32_t th[4], tl[4];
                ldm_x4t(th, addr);
                ldm_x4t(tl, addr + (ST_BL - ST_BH));
                uint32_t bh0[2] = {th[0], th[1]}, bh1[2] = {th[2], th[3]};
                uint32_t bl0[2] = {tl[0], tl[1]}, bl1[2] = {tl[2], tl[3]};
                #pragma unroll
                for (int mf = 0; mf < 2; mf++) {
                    mma16816(acc[mf][g * 2],     ahf[mf], bh0);
                    mma16816(acc[mf][g * 2],     ahf[mf], bl0);
                    mma16816(acc[mf][g * 2],     alf[mf], bh0);
                    mma16816(acc[mf][g * 2 + 1], ahf[mf], bh1);
                    mma16816(acc[mf][g * 2 + 1], ahf[mf], bl1);
                    mma16816(acc[mf][g * 2 + 1], alf[mf], bh1);
                }
            }
        }
        __syncthreads();
    }

    // ---- epilogue: bias + fused L2 row-normalize ----
    #pragma unroll
    for (int mf = 0; mf < 2; mf++)
        #pragma unroll
        for (int nf = 0; nf < 8; nf++) {
            const int n = wn * 64 + nf * 8 + (lane & 3) * 2;
            const float bx = bias[n], by = bias[n + 1];
            acc[mf][nf][0] += bx; acc[mf][nf][1] += by;
            acc[mf][nf][2] += bx; acc[mf][nf][3] += by;
        }

    float* part = (float*)smem;
    #pragma unroll
    for (int mf = 0; mf < 2; mf++) {
        float p0 = 0.0f, p1 = 0.0f;
        #pragma unroll
        for (int nf = 0; nf < 8; nf++) {
            p0 = fmaf(acc[mf][nf][0], acc[mf][nf][0], p0);
            p0 = fmaf(acc[mf][nf][1], acc[mf][nf][1], p0);
            p1 = fmaf(acc[mf][nf][2], acc[mf][nf][2], p1);
            p1 = fmaf(acc[mf][nf][3], acc[mf][nf][3], p1);
        }
        p0 += __shfl_xor_sync(0xffffffffu, p0, 1);
        p0 += __shfl_xor_sync(0xffffffffu, p0, 2);
        p1 += __shfl_xor_sync(0xffffffffu, p1, 1);
        p1 += __shfl_xor_sync(0xffffffffu, p1, 2);
        if ((lane & 3) == 0) {
            const int r = wm * 32 + mf * 16 + (lane >> 2);
            part[wn * 64 + r]     = p0;
            part[wn * 64 + r + 8] = p1;
        }
    }
    __syncthreads();

    #pragma unroll
    for (int mf = 0; mf < 2; mf++) {
        const int r0 = wm * 32 + mf * 16 + (lane >> 2);
        const int r1 = r0 + 8;
        const float s0 = part[r0] + part[64 + r0] + part[128 + r0] + part[192 + r0];
        const float s1 = part[r1] + part[64 + r1] + part[128 + r1] + part[192 + r1];
        const float inv0 = 1.0f / fmaxf(sqrtf(s0), 1e-12f);
        const float inv1 = 1.0f / fmaxf(sqrtf(s1), 1e-12f);
        #pragma unroll
        for (int nf = 0; nf < 8; nf++) {
            const int n = wn * 64 + nf * 8 + (lane & 3) * 2;
            acc[mf][nf][0] *= inv0; acc[mf][nf][1] *= inv0;
            acc[mf][nf][2] *= inv1; acc[mf][nf][3] *= inv1;
            if (isV) {
                split_pair(acc[mf][nf][0], acc[mf][nf][1],
                           &g_vis_hi[(size_t)(m0 + r0) * D_ + n], &g_vis_lo[(size_t)(m0 + r0) * D_ + n]);
                split_pair(acc[mf][nf][2], acc[mf][nf][3],
                           &g_vis_hi[(size_t)(m0 + r1) * D_ + n], &g_vis_lo[(size_t)(m0 + r1) * D_ + n]);
            } else {
                float2 w0; w0.x = acc[mf][nf][0]; w0.y = acc[mf][nf][1];
                float2 w1; w1.x = acc[mf][nf][2]; w1.y = acc[mf][nf][3];
                *(float2*)&g_phrase[(size_t)(m0 + r0) * D_ + n] = w0;
                *(float2*)&g_phrase[(size_t)(m0 + r1) * D_ + n] = w1;
            }
        }
    }

    // ---- phrase CTAs: prototypes = l2norm(proto + normalized phrase), bf16 split ----
    if (!isV) {
        __syncthreads();
        #pragma unroll
        for (int mf = 0; mf < 2; mf++) {
            const int r0l = wm * 32 + mf * 16 + (lane >> 2);
            float p0 = 0.0f, p1 = 0.0f;
            #pragma unroll
            for (int nf = 0; nf < 8; nf++) {
                const int n = wn * 64 + nf * 8 + (lane & 3) * 2;
                const float2 pr0 = *(const float2*)&proto[(size_t)r0l * D_ + n];
                const float2 pr1 = *(const float2*)&proto[(size_t)(r0l + 8) * D_ + n];
                acc[mf][nf][0] += pr0.x; acc[mf][nf][1] += pr0.y;
                acc[mf][nf][2] += pr1.x; acc[mf][nf][3] += pr1.y;
                p0 = fmaf(acc[mf][nf][0], acc[mf][nf][0], p0);
                p0 = fmaf(acc[mf][nf][1], acc[mf][nf][1], p0);
                p1 = fmaf(acc[mf][nf][2], acc[mf][nf][2], p1);
                p1 = fmaf(acc[mf][nf][3], acc[mf][nf][3], p1);
            }
            p0 += __shfl_xor_sync(0xffffffffu, p0, 1);
            p0 += __shfl_xor_sync(0xffffffffu, p0, 2);
            p1 += __shfl_xor_sync(0xffffffffu, p1, 1);
            p1 += __shfl_xor_sync(0xffffffffu, p1, 2);
            if ((lane & 3) == 0) {
                const int r = wm * 32 + mf * 16 + (lane >> 2);
                part[wn * 64 + r]     = p0;
                part[wn * 64 + r + 8] = p1;
            }
        }
        __syncthreads();
        #pragma unroll
        for (int mf = 0; mf < 2; mf++) {
            const int r0 = wm * 32 + mf * 16 + (lane >> 2);
            const int r1 = r0 + 8;
            const float s0 = part[r0] + part[64 + r0] + part[128 + r0] + part[192 + r0];
            const float s1 = part[r1] + part[64 + r1] + part[128 + r1] + part[192 + r1];
            const float inv0 = 1.0f / fmaxf(sqrtf(s0), 1e-12f);
            const float inv1 = 1.0f / fmaxf(sqrtf(s1), 1e-12f);
            #pragma unroll
            for (int nf = 0; nf < 8; nf++) {
                const int n = wn * 64 + nf * 8 + (lane & 3) * 2;
                split_pair(acc[mf][nf][0] * inv0, acc[mf][nf][1] * inv0,
                           &g_proto_hi[(size_t)(m0 + r0) * D_ + n], &g_proto_lo[(size_t)(m0 + r0) * D_ + n]);
                split_pair(acc[mf][nf][2] * inv1, acc[mf][nf][3] * inv1,
                           &g_proto_hi[(size_t)(m0 + r1) * D_ + n], &g_proto_lo[(size_t)(m0 + r1) * D_ + n]);
            }
        }
    }
}

// ---------------- HMMA attention ----------------
// block = (og: 8 o's, b). 256 threads, 8 warps.
#define AS_VH 0
#define AS_VL 32768
#define AS_PH 65536
#define AS_PL 73728
#define AS_S  81920
#define AS_EH 114688
#define AS_EL 147712
#define AS_RLOG 180736
#define AS_RE   180992
#define AS_RL   181024
#define AS_SINV 181056
#define ATT_SMEM 181120

__global__ __launch_bounds__(256, 1) void k_attn_mma(
    const float* __restrict__ labels, const float* __restrict__ Wc,
    const float* __restrict__ bcp, float* __restrict__ out)
{
    extern __shared__ char smem[];
    const uint32_t sb = smem_u32(smem);
    const int tid = threadIdx.x, lane = tid & 31, w = tid >> 5;
    const int og = blockIdx.x, b = blockIdx.y;
    const int row0 = b * O_ + og * 8;

    // load 8 proto rows hi/lo (swizzled, 512B rows)
    {
        const int r = tid >> 5, ch = tid & 31;
        const uint32_t off = (uint32_t)(r * 512 + ((ch ^ (r & 7)) << 4));
        const size_t src = (size_t)(row0 + r) * D_ + ch * 8;
        cpa16(sb + AS_PH + off, g_proto_hi + src);
        cpa16(sb + AS_PL + off, g_proto_lo + src);
    }
    CP_COMMIT();

    const __nv_bfloat16* vh = g_vis_hi + (size_t)b * N_ * D_;
    const __nv_bfloat16* vl = g_vis_lo + (size_t)b * N_ * D_;
    float* S = (float*)(smem + AS_S);

    // ---- pass 1: logits S[8][1024] via mma ----
    for (int tile = 0; tile < 16; tile++) {
        for (int i = tid; i < 2048; i += 256) {
            const int r = i >> 5, ch = i & 31;
            const uint32_t off = (uint32_t)(r * 512 + ((ch ^ (r & 7)) << 4));
            const size_t src = (size_t)(tile * 64 + r) * D_ + ch * 8;
            cpa16(sb + AS_VH + off, vh + src);
            cpa16(sb + AS_VL + off, vl + src);
        }
        CP_COMMIT(); CP_WAIT0();
        __syncthreads();

        float sacc[4] = {0.f, 0.f, 0.f, 0.f};
        #pragma unroll
        for (int ks = 0; ks < 16; ks++) {
            const int arow = ((lane >> 3) & 1) * 8 + (lane & 7);
            const int ach = ks * 2 + (lane >> 4);
            const uint32_t aoff = (uint32_t)(arow * 512 + ((ach ^ (arow & 7)) << 4));
            uint32_t ah[4], al[4];
            ldm_x4(ah, sb + AS_PH + aoff);
            ldm_x4(al, sb + AS_PL + aoff);
            const int brow = w * 8 + (lane & 7);
            const int bch = ks * 2 + ((lane >> 3) & 1);
            const uint32_t boff = (uint32_t)(brow * 512 + ((bch ^ (brow & 7)) << 4));
            uint32_t bh[2], bl[2];
            ldm_x2(bh, sb + AS_VH + boff);
            ldm_x2(bl, sb + AS_VL + boff);
            mma16816(sacc, ah, bh);
            mma16816(sacc, ah, bl);
            mma16816(sacc, al, bh);
        }
        const int r0 = lane >> 2;               // 0..7 (rows 8..15 of frag unused)
        const int n = tile * 64 + w * 8 + (lane & 3) * 2;
        S[r0 * N_ + n]     = sacc[0];
        S[r0 * N_ + n + 1] = sacc[1];
        __syncthreads();
    }

    // ---- softmax: warp w owns row w. store unscaled exp as bf16 hi/lo A-matrix ----
    {
        float* Srow = S + w * N_;
        float4 vals[8];
        #pragma unroll
        for (int j = 0; j < 8; j++)
            vals[j] = *(float4*)&Srow[lane * 4 + 128 * j];
        float mx = -1e30f;
        #pragma unroll
        for (int j = 0; j < 8; j++)
            mx = fmaxf(mx, fmaxf(fmaxf(vals[j].x, vals[j].y), fmaxf(vals[j].z, vals[j].w)));
        mx = warp_max(mx);
        float sum = 0.0f;
        #pragma unroll
        for (int j = 0; j < 8; j++) {
            vals[j].x = expf(vals[j].x - mx);
            vals[j].y = expf(vals[j].y - mx);
            vals[j].z = expf(vals[j].z - mx);
            vals[j].w = expf(vals[j].w - mx);
            sum += vals[j].x + vals[j].y + vals[j].z + vals[j].w;
        }
        sum = warp_sum(sum);
        const float inv = 1.0f / sum;
        float ent = 0.0f;
        float* outA = out + ATT_OFF + (size_t)(row0 + w) * N_;
        #pragma unroll
        for (int j = 0; j < 8; j++) {
            const int n = lane * 4 + 128 * j;
            // store unscaled exps bf16 hi/lo (E matrix, row stride 1032 bf16)
            split_pair(vals[j].x, vals[j].y,
                       (__nv_bfloat16*)(smem + AS_EH + w * 2064 + n * 2),
                       (__nv_bfloat16*)(smem + AS_EL + w * 2064 + n * 2));
            split_pair(vals[j].z, vals[j].w,
                       (__nv_bfloat16*)(smem + AS_EH + w * 2064 + (n + 2) * 2),
                       (__nv_bfloat16*)(smem + AS_EL + w * 2064 + (n + 2) * 2));
            float4 p;
            p.x = vals[j].x * inv; p.y = vals[j].y * inv;
            p.z = vals[j].z * inv; p.w = vals[j].w * inv;
            *(float4*)&outA[n] = p;
            ent += p.x * logf(fmaxf(p.x, 1e-8f));
            ent += p.y * logf(fmaxf(p.y, 1e-8f));
            ent += p.z * logf(fmaxf(p.z, 1e-8f));
            ent += p.w * logf(fmaxf(p.w, 1e-8f));
        }
        ent = warp_sum(ent);
        if (lane == 0) {
            ((float*)(smem + AS_SINV))[w] = inv;
            ((float*)(smem + AS_RE))[w] = ent;
        }
    }
    __syncthreads();

    // ---- pass 3: evidence = E @ visual via mma (warp w owns d-slice w*32..+32) ----
    float eacc[4][4];
    #pragma unroll
    for (int i = 0; i < 4; i++)
        #pragma unroll
        for (int j = 0; j < 4; j++) eacc[i][j] = 0.0f;

    for (int tile = 0; tile < 16; tile++) {
        for (int i = tid; i < 2048; i += 256) {
            const int r = i >> 5, ch = i & 31;
            const uint32_t off = (uint32_t)(r * 512 + ((ch ^ (r & 7)) << 4));
            const size_t src = (size_t)(tile * 64 + r) * D_ + ch * 8;
            cpa16(sb + AS_VH + off, vh + src);
            cpa16(sb + AS_VL + off, vl + src);
        }
        CP_COMMIT(); CP_WAIT0();
        __syncthreads();

        #pragma unroll
        for (int ksl = 0; ksl < 4; ksl++) {
            const int kg = tile * 4 + ksl;
            const int arow = ((lane >> 3) & 1) * 8 + (lane & 7);
            const int ach = kg * 2 + (lane >> 4);
            const uint32_t aoff = (uint32_t)(arow * 2064 + ach * 16);
            uint32_t ah[4], al[4];
            ldm_x4(ah, sb + AS_EH + aoff);
            ldm_x4(al, sb + AS_EL + aoff);
            #pragma unroll
            for (int g = 0; g < 2; g++) {
                const int brow = ksl * 16 + ((lane >> 3) & 1) * 8 + (lane & 7);
                const int bch = w * 4 + g * 2 + (lane >> 4);
                const uint32_t boff = (uint32_t)(brow * 512 + ((bch ^ (brow & 7)) << 4));
                uint32_t th[4], tl[4];
                ldm_x4t(th, sb + AS_VH + boff);
                ldm_x4t(tl, sb + AS_VL + boff);
                uint32_t bh0[2] = {th[0], th[1]}, bh1[2] = {th[2], th[3]};
                uint32_t bl0[2] = {tl[0], tl[1]}, bl1[2] = {tl[2], tl[3]};
                mma16816(eacc[g * 2],     ah, bh0);
                mma16816(eacc[g * 2],     ah, bl0);
                mma16816(eacc[g * 2],     al, bh0);
                mma16816(eacc[g * 2 + 1], ah, bh1);
                mma16816(eacc[g * 2 + 1], ah, bl1);
                mma16816(eacc[g * 2 + 1], al, bh1);
            }
        }
        __syncthreads();
    }

    // ---- epilogue: scale by invS, write evidence, logits, losses ----
    {
        const int r0 = lane >> 2;                 // 0..7
        const int grow = row0 + r0;
        const float inv = ((float*)(smem + AS_SINV))[r0];
        const float lab = labels[grow];
        float lp = 0.0f, lsum = 0.0f;
        #pragma unroll
        for (int nf = 0; nf < 4; nf++) {
            const int d = w * 32 + nf * 8 + (lane & 3) * 2;
            const float e0 = eacc[nf][0] * inv;
            const float e1 = eacc[nf][1] * inv;
            float2 ev2; ev2.x = e0; ev2.y = e1;
            *(float2*)&out[EV_OFF + (size_t)grow * D_ + d] = ev2;
            lp += e0 * Wc[d] + e1 * Wc[d + 1];
            const float2 ph = *(const float2*)&g_phrase[(size_t)grow * D_ + d];
            const float d0 = e0 - lab * ph.x;
            const float d1 = e1 - lab * ph.y;
            lsum += d0 * d0 + d1 * d1;
        }
        lp += __shfl_xor_sync(0xffffffffu, lp, 1);
        lp += __shfl_xor_sync(0xffffffffu, lp, 2);
        if ((lane & 3) == 0) ((float*)(smem + AS_RLOG))[w * 8 + r0] = lp;
        lsum = warp_sum(lsum);
        if (lane == 0) ((float*)(smem + AS_RL))[w] = lsum;
    }
    __syncthreads();

    if (tid < 8) {
        float s = 0.0f;
        #pragma unroll
        for (int ww = 0; ww < 8; ww++) s += ((float*)(smem + AS_RLOG))[ww * 8 + tid];
        out[LOG_OFF + row0 + tid] = s + bcp[0];
    }
    if (tid == 0) {
        float s = 0.0f, e = 0.0f;
        #pragma unroll
        for (int i = 0; i < 8; i++) {
            s += ((float*)(smem + AS_RL))[i];
            e += ((float*)(smem + AS_RE))[i];
        }
        atomicAdd(&g_accum[0], s);
        atomicAdd(&g_accum[1], e);
    }
}

__global__ void k_finalize(float* __restrict__ out) {
    const float proto_loss = g_accum[0] / (float)(B_ * O_ * D_);
    const float sparse_loss = -g_accum[1] / (float)(B_ * O_);
    out[LOSS_OFF] = proto_loss + 0.01f * sparse_loss;
}

// ---------------- launch ----------------
extern "C" void kernel_launch(void* const* d_in, const int* in_sizes, int n_in,
                              void* d_out, int out_size)
{
    (void)in_sizes; (void)n_in; (void)out_size;
    const float* visual_tokens = (const float*)d_in[0];
    const float* phrase_states = (const float*)d_in[1];
    const float* labels        = (const float*)d_in[2];
    const float* Wv            = (const float*)d_in[3];
    const float* bv            = (const float*)d_in[4];
    const float* Wp            = (const float*)d_in[5];
    const float* bp            = (const float*)d_in[6];
    const float* proto         = (const float*)d_in[7];
    const float* Wc            = (const float*)d_in[8];
    const float* bc            = (const float*)d_in[9];
    float* out = (float*)d_out;

    __nv_bfloat16 *ah, *al, *pah, *pal;
    cudaGetSymbolAddress((void**)&ah,  g_a_hi);
    cudaGetSymbolAddress((void**)&al,  g_a_lo);
    cudaGetSymbolAddress((void**)&pah, g_pa_hi);
    cudaGetSymbolAddress((void**)&pal, g_pa_lo);

    cudaFuncSetAttribute(k_gemm_mma, cudaFuncAttributeMaxDynamicSharedMemorySize, GEMM_SMEM);
    cudaFuncSetAttribute(k_attn_mma, cudaFuncAttributeMaxDynamicSharedMemorySize, ATT_SMEM);

    k_zero<<<1, 1>>>();
    k_split<<<4096, 256>>>(visual_tokens, ah, al, MV * H_ / 4);
    k_split<<<1024, 256>>>(phrase_states, pah, pal, MP * H_ / 4);
    k_split_w<<<512, 256>>>(Wv, Wp);
    k_gemm_mma<<<MV / 64 + MP / 64, 256, GEMM_SMEM>>>(bv, bp, proto);
    k_attn_mma<<<dim3(8, B_), 256, ATT_SMEM>>>(labels, Wc, bc, out);
    k_finalize<<<1, 1>>>(out);
}

// round 12
// speedup vs baseline: 2.4702x; 1.2833x over previous
#include <cuda_runtime.h>
#include <cuda_bf16.h>
#include <cstdint>

#define B_  16
#define N_  1024
#define O_  64
#define H_  1024
#define D_  256

#define MV  (B_ * N_)      // 16384
#define MP  (B_ * O_)      // 1024

#define LOG_OFF  0
#define ATT_OFF  (B_ * O_)
#define EV_OFF   (ATT_OFF + B_ * O_ * N_)
#define LOSS_OFF (EV_OFF + B_ * O_ * D_)

// ---------------- device scratch ----------------
__device__ float g_phrase[MP * D_];   // normalized phrase fp32 (for loss)
__device__ float g_accum[2];

__device__ __align__(16) __nv_bfloat16 g_wv_hi[H_ * D_];
__device__ __align__(16) __nv_bfloat16 g_wv_lo[H_ * D_];
__device__ __align__(16) __nv_bfloat16 g_wp_hi[H_ * D_];
__device__ __align__(16) __nv_bfloat16 g_wp_lo[H_ * D_];

__device__ __align__(16) __nv_bfloat16 g_vis_hi[MV * D_];
__device__ __align__(16) __nv_bfloat16 g_vis_lo[MV * D_];
__device__ __align__(16) __nv_bfloat16 g_proto_hi[MP * D_];
__device__ __align__(16) __nv_bfloat16 g_proto_lo[MP * D_];

__global__ void k_zero() { g_accum[0] = 0.0f; g_accum[1] = 0.0f; }

// ---------------- helpers ----------------
__device__ __forceinline__ uint32_t smem_u32(const void* p) {
    uint32_t a;
    asm("{ .reg .u64 t; cvta.to.shared.u64 t, %1; cvt.u32.u64 %0, t; }" : "=r"(a) : "l"(p));
    return a;
}
__device__ __forceinline__ void cpa16(uint32_t s, const void* g) {
    asm volatile("cp.async.cg.shared.global [%0], [%1], 16;" :: "r"(s), "l"(g));
}
#define CP_COMMIT() asm volatile("cp.async.commit_group;" ::: "memory")
#define CP_WAIT1()  asm volatile("cp.async.wait_group 1;" ::: "memory")
#define CP_WAIT0()  asm volatile("cp.async.wait_group 0;" ::: "memory")

__device__ __forceinline__ void ldm_x4(uint32_t* r, uint32_t a) {
    asm volatile("ldmatrix.sync.aligned.m8n8.x4.shared.b16 {%0,%1,%2,%3}, [%4];"
        : "=r"(r[0]), "=r"(r[1]), "=r"(r[2]), "=r"(r[3]) : "r"(a));
}
__device__ __forceinline__ void ldm_x2(uint32_t* r, uint32_t a) {
    asm volatile("ldmatrix.sync.aligned.m8n8.x2.shared.b16 {%0,%1}, [%2];"
        : "=r"(r[0]), "=r"(r[1]) : "r"(a));
}
__device__ __forceinline__ void ldm_x4t(uint32_t* r, uint32_t a) {
    asm volatile("ldmatrix.sync.aligned.m8n8.x4.trans.shared.b16 {%0,%1,%2,%3}, [%4];"
        : "=r"(r[0]), "=r"(r[1]), "=r"(r[2]), "=r"(r[3]) : "r"(a));
}
__device__ __forceinline__ void mma16816(float* c, const uint32_t* a, const uint32_t* b) {
    asm volatile(
        "mma.sync.aligned.m16n8k16.row.col.f32.bf16.bf16.f32 "
        "{%0,%1,%2,%3}, {%4,%5,%6,%7}, {%8,%9}, {%0,%1,%2,%3};"
        : "+f"(c[0]), "+f"(c[1]), "+f"(c[2]), "+f"(c[3])
        : "r"(a[0]), "r"(a[1]), "r"(a[2]), "r"(a[3]), "r"(b[0]), "r"(b[1]));
}

__device__ __forceinline__ float warp_sum(float v) {
    #pragma unroll
    for (int o = 16; o > 0; o >>= 1) v += __shfl_xor_sync(0xffffffffu, v, o);
    return v;
}

__device__ __forceinline__ void split_pair(float x, float y, __nv_bfloat16* hi, __nv_bfloat16* lo) {
    __nv_bfloat162 h, l;
    h.x = __float2bfloat16(x); h.y = __float2bfloat16(y);
    l.x = __float2bfloat16(x - __bfloat162float(h.x));
    l.y = __float2bfloat16(y - __bfloat162float(h.y));
    *(__nv_bfloat162*)hi = h;
    *(__nv_bfloat162*)lo = l;
}

__device__ __forceinline__ uint32_t bf2pack(float a, float b) {
    __nv_bfloat162 h;
    h.x = __float2bfloat16(a); h.y = __float2bfloat16(b);
    return *(uint32_t*)&h;
}

// split 8 fp32 -> 16B hi + 16B lo
__device__ __forceinline__ void split8(const float4& A, const float4& B, uint4& hi, uint4& lo) {
    hi.x = bf2pack(A.x, A.y); hi.y = bf2pack(A.z, A.w);
    hi.z = bf2pack(B.x, B.y); hi.w = bf2pack(B.z, B.w);
    __nv_bfloat162 h;
    *(uint32_t*)&h = hi.x; lo.x = bf2pack(A.x - __bfloat162float(h.x), A.y - __bfloat162float(h.y));
    *(uint32_t*)&h = hi.y; lo.y = bf2pack(A.z - __bfloat162float(h.x), A.w - __bfloat162float(h.y));
    *(uint32_t*)&h = hi.z; lo.z = bf2pack(B.x - __bfloat162float(h.x), B.y - __bfloat162float(h.y));
    *(uint32_t*)&h = hi.w; lo.w = bf2pack(B.z - __bfloat162float(h.x), B.w - __bfloat162float(h.y));
}

__device__ __forceinline__ void split_one(const float* __restrict__ x,
                                          __nv_bfloat16* __restrict__ hi,
                                          __nv_bfloat16* __restrict__ lo, int i)
{
    float4 v = ((const float4*)x)[i];
    uint4 h, l;
    split8(v, v, h, l);
    ((uint32_t*)hi)[i * 2]     = h.x;
    ((uint32_t*)hi)[i * 2 + 1] = h.y;
    ((uint32_t*)lo)[i * 2]     = l.x;
    ((uint32_t*)lo)[i * 2 + 1] = l.y;
}

__global__ __launch_bounds__(256) void k_split_w(const float* __restrict__ Wv,
                                                 const float* __restrict__ Wp)
{
    const int n4 = H_ * D_ / 4;
    for (int i = blockIdx.x * blockDim.x + threadIdx.x; i < 2 * n4; i += gridDim.x * blockDim.x) {
        if (i < n4) split_one(Wv, g_wv_hi, g_wv_lo, i);
        else        split_one(Wp, g_wp_hi, g_wp_lo, i - n4);
    }
}

// ---------------- mma.sync GEMM, BM=64 BN=256 BK=32, 2 CTA/SM ----------------
// A loaded fp32 from inputs; split to bf16 hi/lo in-kernel (no split pre-pass).
#define NSTAGE (H_ / 32)
#define ST_AH 0
#define ST_AL 4096
#define ST_BH 8192
#define ST_BL 24576
#define SMEM_STAGE 40960
#define GEMM_SMEM (2 * SMEM_STAGE)

__global__ __launch_bounds__(256, 2) void k_gemm_mma(const float* __restrict__ visA,
                                                     const float* __restrict__ phrA,
                                                     const float* __restrict__ bv,
                                                     const float* __restrict__ bp,
                                                     const float* __restrict__ proto)
{
    extern __shared__ char smem[];
    const uint32_t sb = smem_u32(smem);
    const int tid = threadIdx.x;
    const int lane = tid & 31;
    const int wid = tid >> 5;
    const int wm = wid & 1;
    const int wn = wid >> 1;

    const bool isV = blockIdx.x < (MV / 64);
    const float* Afp;
    const __nv_bfloat16 *Bh, *Bl;
    const float* bias;
    int m0;
    if (isV) { Afp = visA; Bh = g_wv_hi; Bl = g_wv_lo; bias = bv; m0 = blockIdx.x * 64; }
    else     { Afp = phrA; Bh = g_wp_hi; Bl = g_wp_lo; bias = bp; m0 = (blockIdx.x - MV / 64) * 64; }

    const int a_r = tid >> 2;              // 0..63
    const int a_c = tid & 3;               // chunk (8 floats -> 16B bf16)
    const uint32_t a_so = (uint32_t)(a_r * 64 + ((a_c ^ ((a_r >> 1) & 3)) << 4));
    const float* Arow = Afp + (size_t)(m0 + a_r) * H_ + a_c * 8;

    const int b_r = tid >> 3;
    const int b_c = tid & 7;
    uint32_t b_so[4];
    #pragma unroll
    for (int q = 0; q < 4; q++)
        b_so[q] = (uint32_t)(b_r * 512 + (((b_c + q * 8) ^ (b_r & 7)) << 4));

    float acc[2][8][4];
    #pragma unroll
    for (int i = 0; i < 2; i++)
        #pragma unroll
        for (int j = 0; j < 8; j++)
            #pragma unroll
            for (int k = 0; k < 4; k++) acc[i][j][k] = 0.0f;

    // prologue: A(0) fp32 in regs, B(0) cp.async
    float4 fa0 = *(const float4*)(Arow);
    float4 fa1 = *(const float4*)(Arow + 4);
    #pragma unroll
    for (int q = 0; q < 4; q++) {
        cpa16(sb + ST_BH + b_so[q], Bh + (size_t)b_r * D_ + (b_c + q * 8) * 8);
        cpa16(sb + ST_BL + b_so[q], Bl + (size_t)b_r * D_ + (b_c + q * 8) * 8);
    }
    CP_COMMIT();

    for (int s = 0; s < NSTAGE; s++) {
        // split & store A(s)
        {
            uint4 h, l;
            split8(fa0, fa1, h, l);
            const uint32_t ast = (uint32_t)((s & 1) * SMEM_STAGE);
            *(uint4*)(smem + ast + ST_AH + a_so) = h;
            *(uint4*)(smem + ast + ST_AL + a_so) = l;
        }
        if (s + 1 < NSTAGE) {
            const int k0 = (s + 1) * 32;
            fa0 = *(const float4*)(Arow + k0);
            fa1 = *(const float4*)(Arow + k0 + 4);
            const uint32_t st = sb + ((s + 1) & 1) * SMEM_STAGE;
            #pragma unroll
            for (int q = 0; q < 4; q++) {
                cpa16(st + ST_BH + b_so[q], Bh + (size_t)(k0 + b_r) * D_ + (b_c + q * 8) * 8);
                cpa16(st + ST_BL + b_so[q], Bl + (size_t)(k0 + b_r) * D_ + (b_c + q * 8) * 8);
            }
        }
        CP_COMMIT();
        CP_WAIT1();
        __syncthreads();

        const uint32_t base = sb + (s & 1) * SMEM_STAGE;

        #pragma unroll
        for (int ks = 0; ks < 2; ks++) {
            uint32_t ahf[2][4], alf[2][4];
            #pragma unroll
            for (int mf = 0; mf < 2; mf++) {
                const int row = wm * 32 + mf * 16 + ((lane >> 3) & 1) * 8 + (lane & 7);
                const int ch  = ks * 2 + (lane >> 4);
                const uint32_t addr = base + ST_AH + (uint32_t)(row * 64 + ((ch ^ ((row >> 1) & 3)) << 4));
                ldm_x4(ahf[mf], addr);
                ldm_x4(alf[mf], addr + (ST_AL - ST_AH));
            }
            #pragma unroll
            for (int g = 0; g < 4; g++) {
                const int row = ks * 16 + ((lane >> 3) & 1) * 8 + (lane & 7);
                const int ch  = wn * 8 + g * 2 + (lane >> 4);
                const uint32_t addr = base + ST_BH + (uint32_t)(row * 512 + ((ch ^ (row & 7)) << 4));
                uint32_t th[4], tl[4];
                ldm_x4t(th, addr);
                ldm_x4t(tl, addr + (ST_BL - ST_BH));
                uint32_t bh0[2] = {th[0], th[1]}, bh1[2] = {th[2], th[3]};
                uint32_t bl0[2] = {tl[0], tl[1]}, bl1[2] = {tl[2], tl[3]};
                #pragma unroll
                for (int mf = 0; mf < 2; mf++) {
                    mma16816(acc[mf][g * 2],     ahf[mf], bh0);
                    mma16816(acc[mf][g * 2],     ahf[mf], bl0);
                    mma16816(acc[mf][g * 2],     alf[mf], bh0);
                    mma16816(acc[mf][g * 2 + 1], ahf[mf], bh1);
                    mma16816(acc[mf][g * 2 + 1], ahf[mf], bl1);
                    mma16816(acc[mf][g * 2 + 1], alf[mf], bh1);
                }
            }
        }
        __syncthreads();
    }

    // ---- epilogue: bias + fused L2 row-normalize ----
    #pragma unroll
    for (int mf = 0; mf < 2; mf++)
        #pragma unroll
        for (int nf = 0; nf < 8; nf++) {
            const int n = wn * 64 + nf * 8 + (lane & 3) * 2;
            const float bx = bias[n], by = bias[n + 1];
            acc[mf][nf][0] += bx; acc[mf][nf][1] += by;
            acc[mf][nf][2] += bx; acc[mf][nf][3] += by;
        }

    float* part = (float*)smem;
    #pragma unroll
    for (int mf = 0; mf < 2; mf++) {
        float p0 = 0.0f, p1 = 0.0f;
        #pragma unroll
        for (int nf = 0; nf < 8; nf++) {
            p0 = fmaf(acc[mf][nf][0], acc[mf][nf][0], p0);
            p0 = fmaf(acc[mf][nf][1], acc[mf][nf][1], p0);
            p1 = fmaf(acc[mf][nf][2], acc[mf][nf][2], p1);
            p1 = fmaf(acc[mf][nf][3], acc[mf][nf][3], p1);
        }
        p0 += __shfl_xor_sync(0xffffffffu, p0, 1);
        p0 += __shfl_xor_sync(0xffffffffu, p0, 2);
        p1 += __shfl_xor_sync(0xffffffffu, p1, 1);
        p1 += __shfl_xor_sync(0xffffffffu, p1, 2);
        if ((lane & 3) == 0) {
            const int r = wm * 32 + mf * 16 + (lane >> 2);
            part[wn * 64 + r]     = p0;
            part[wn * 64 + r + 8] = p1;
        }
    }
    __syncthreads();

    #pragma unroll
    for (int mf = 0; mf < 2; mf++) {
        const int r0 = wm * 32 + mf * 16 + (lane >> 2);
        const int r1 = r0 + 8;
        const float s0 = part[r0] + part[64 + r0] + part[128 + r0] + part[192 + r0];
        const float s1 = part[r1] + part[64 + r1] + part[128 + r1] + part[192 + r1];
        const float inv0 = 1.0f / fmaxf(sqrtf(s0), 1e-12f);
        const float inv1 = 1.0f / fmaxf(sqrtf(s1), 1e-12f);
        #pragma unroll
        for (int nf = 0; nf < 8; nf++) {
            const int n = wn * 64 + nf * 8 + (lane & 3) * 2;
            acc[mf][nf][0] *= inv0; acc[mf][nf][1] *= inv0;
            acc[mf][nf][2] *= inv1; acc[mf][nf][3] *= inv1;
            if (isV) {
                split_pair(acc[mf][nf][0], acc[mf][nf][1],
                           &g_vis_hi[(size_t)(m0 + r0) * D_ + n], &g_vis_lo[(size_t)(m0 + r0) * D_ + n]);
                split_pair(acc[mf][nf][2], acc[mf][nf][3],
                           &g_vis_hi[(size_t)(m0 + r1) * D_ + n], &g_vis_lo[(size_t)(m0 + r1) * D_ + n]);
            } else {
                float2 w0; w0.x = acc[mf][nf][0]; w0.y = acc[mf][nf][1];
                float2 w1; w1.x = acc[mf][nf][2]; w1.y = acc[mf][nf][3];
                *(float2*)&g_phrase[(size_t)(m0 + r0) * D_ + n] = w0;
                *(float2*)&g_phrase[(size_t)(m0 + r1) * D_ + n] = w1;
            }
        }
    }

    if (!isV) {
        __syncthreads();
        #pragma unroll
        for (int mf = 0; mf < 2; mf++) {
            const int r0l = wm * 32 + mf * 16 + (lane >> 2);
            float p0 = 0.0f, p1 = 0.0f;
            #pragma unroll
            for (int nf = 0; nf < 8; nf++) {
                const int n = wn * 64 + nf * 8 + (lane & 3) * 2;
                const float2 pr0 = *(const float2*)&proto[(size_t)r0l * D_ + n];
                const float2 pr1 = *(const float2*)&proto[(size_t)(r0l + 8) * D_ + n];
                acc[mf][nf][0] += pr0.x; acc[mf][nf][1] += pr0.y;
                acc[mf][nf][2] += pr1.x; acc[mf][nf][3] += pr1.y;
                p0 = fmaf(acc[mf][nf][0], acc[mf][nf][0], p0);
                p0 = fmaf(acc[mf][nf][1], acc[mf][nf][1], p0);
                p1 = fmaf(acc[mf][nf][2], acc[mf][nf][2], p1);
                p1 = fmaf(acc[mf][nf][3], acc[mf][nf][3], p1);
            }
            p0 += __shfl_xor_sync(0xffffffffu, p0, 1);
            p0 += __shfl_xor_sync(0xffffffffu, p0, 2);
            p1 += __shfl_xor_sync(0xffffffffu, p1, 1);
            p1 += __shfl_xor_sync(0xffffffffu, p1, 2);
            if ((lane & 3) == 0) {
                const int r = wm * 32 + mf * 16 + (lane >> 2);
                part[wn * 64 + r]     = p0;
                part[wn * 64 + r + 8] = p1;
            }
        }
        __syncthreads();
        #pragma unroll
        for (int mf = 0; mf < 2; mf++) {
            const int r0 = wm * 32 + mf * 16 + (lane >> 2);
            const int r1 = r0 + 8;
            const float s0 = part[r0] + part[64 + r0] + part[128 + r0] + part[192 + r0];
            const float s1 = part[r1] + part[64 + r1] + part[128 + r1] + part[192 + r1];
            const float inv0 = 1.0f / fmaxf(sqrtf(s0), 1e-12f);
            const float inv1 = 1.0f / fmaxf(sqrtf(s1), 1e-12f);
            #pragma unroll
            for (int nf = 0; nf < 8; nf++) {
                const int n = wn * 64 + nf * 8 + (lane & 3) * 2;
                split_pair(acc[mf][nf][0] * inv0, acc[mf][nf][1] * inv0,
                           &g_proto_hi[(size_t)(m0 + r0) * D_ + n], &g_proto_lo[(size_t)(m0 + r0) * D_ + n]);
                split_pair(acc[mf][nf][2] * inv1, acc[mf][nf][3] * inv1,
                           &g_proto_hi[(size_t)(m0 + r1) * D_ + n], &g_proto_lo[(size_t)(m0 + r1) * D_ + n]);
            }
        }
    }
}

// ---------------- single-pass flash attention (HMMA) ----------------
// block = (og: 8 o's, b). 256 threads, 8 warps. V tiles read ONCE, double-buffered.
#define AV_ST(st) ((st) * 65536)           // VH at +0 (32KB), VL at +32768
#define AS_PH 131072
#define AS_PL 139264
#define AS_S  147456                        // 8 rows x 1032 fp32 (padded stride)
#define S_STRIDE 1032
#define AS_EH 180480                        // 16 rows x 128B (8 valid)
#define AS_EL 182528
#define AS_RED 184576
#define RED_M    (AS_RED + 0)
#define RED_S    (AS_RED + 32)
#define RED_F    (AS_RED + 64)
#define RED_WMAX (AS_RED + 96)              // [8 rows][8 warps]
#define RED_ESUM (AS_RED + 352)             // [8 rows][8 warps]
#define RED_RE   (AS_RED + 608)
#define RED_RLOG (AS_RED + 640)             // [8 warps][8 rows]
#define RED_RL   (AS_RED + 896)
#define ATT_SMEM (AS_RED + 960)

__global__ __launch_bounds__(256, 1) void k_attn_mma(
    const float* __restrict__ labels, const float* __restrict__ Wc,
    const float* __restrict__ bcp, float* __restrict__ out)
{
    extern __shared__ char smem[];
    const uint32_t sb = smem_u32(smem);
    const int tid = threadIdx.x, lane = tid & 31, w = tid >> 5;
    const int og = blockIdx.x, b = blockIdx.y;
    const int row0 = b * O_ + og * 8;
    const int r0 = lane >> 2;

    // proto rows (group 0)
    {
        const int r = tid >> 5, ch = tid & 31;
        const uint32_t off = (uint32_t)(r * 512 + ((ch ^ (r & 7)) << 4));
        const size_t src = (size_t)(row0 + r) * D_ + ch * 8;
        cpa16(sb + AS_PH + off, g_proto_hi + src);
        cpa16(sb + AS_PL + off, g_proto_lo + src);
    }
    CP_COMMIT();

    const __nv_bfloat16* vh = g_vis_hi + (size_t)b * N_ * D_;
    const __nv_bfloat16* vl = g_vis_lo + (size_t)b * N_ * D_;
    float* S = (float*)(smem + AS_S);
    float* mred = (float*)(smem + RED_M);
    float* sred = (float*)(smem + RED_S);
    float* fred = (float*)(smem + RED_F);
    float* wmax = (float*)(smem + RED_WMAX);
    float* esum = (float*)(smem + RED_ESUM);

    if (tid < 8) { mred[tid] = -1e30f; sred[tid] = 0.0f; }

    // V tile 0 (group 1)
    {
        const uint32_t vb = sb + AV_ST(0);
        for (int i = tid; i < 2048; i += 256) {
            const int r = i >> 5, ch = i & 31;
            const uint32_t off = (uint32_t)(r * 512 + ((ch ^ (r & 7)) << 4));
            const size_t src = (size_t)r * D_ + ch * 8;
            cpa16(vb + off, vh + src);
            cpa16(vb + 32768 + off, vl + src);
        }
    }
    CP_COMMIT();

    float eacc[4][4];
    #pragma unroll
    for (int i = 0; i < 4; i++)
        #pragma unroll
        for (int j = 0; j < 4; j++) eacc[i][j] = 0.0f;

    for (int tile = 0; tile < 16; tile++) {
        if (tile + 1 < 16) {
            const uint32_t vb = sb + AV_ST((tile + 1) & 1);
            for (int i = tid; i < 2048; i += 256) {
                const int r = i >> 5, ch = i & 31;
                const uint32_t off = (uint32_t)(r * 512 + ((ch ^ (r & 7)) << 4));
                const size_t src = (size_t)((tile + 1) * 64 + r) * D_ + ch * 8;
                cpa16(vb + off, vh + src);
                cpa16(vb + 32768 + off, vl + src);
            }
            CP_COMMIT();
            CP_WAIT1();
        } else {
            CP_WAIT0();
        }
        __syncthreads();

        const uint32_t vbase = sb + AV_ST(tile & 1);

        // ---- logits for this tile ----
        float sacc[4] = {0.f, 0.f, 0.f, 0.f};
        #pragma unroll
        for (int ks = 0; ks < 16; ks++) {
            const int arow = ((lane >> 3) & 1) * 8 + (lane & 7);
            const int ach = ks * 2 + (lane >> 4);
            const uint32_t aoff = (uint32_t)(arow * 512 + ((ach ^ (arow & 7)) << 4));
            uint32_t ah[4], al[4];
            ldm_x4(ah, sb + AS_PH + aoff);
            ldm_x4(al, sb + AS_PL + aoff);
            const int brow = w * 8 + (lane & 7);
            const int bch = ks * 2 + ((lane >> 3) & 1);
            const uint32_t boff = (uint32_t)(brow * 512 + ((bch ^ (brow & 7)) << 4));
            uint32_t bh[2], bl[2];
            ldm_x2(bh, vbase + boff);
            ldm_x2(bl, vbase + 32768 + boff);
            mma16816(sacc, ah, bh);
            mma16816(sacc, ah, bl);
            mma16816(sacc, al, bh);
        }

        // ---- online softmax bookkeeping ----
        float tmax = fmaxf(sacc[0], sacc[1]);
        tmax = fmaxf(tmax, __shfl_xor_sync(0xffffffffu, tmax, 1));
        tmax = fmaxf(tmax, __shfl_xor_sync(0xffffffffu, tmax, 2));
        if ((lane & 3) == 0) wmax[r0 * 8 + w] = tmax;
        __syncthreads();
        if (tid < 8) {
            float mx = mred[tid];
            #pragma unroll
            for (int ww = 0; ww < 8; ww++) mx = fmaxf(mx, wmax[tid * 8 + ww]);
            fred[tid] = expf(mred[tid] - mx);
            mred[tid] = mx;
        }
        __syncthreads();

        const float mrow = mred[r0];
        const float e0 = expf(sacc[0] - mrow);
        const float e1 = expf(sacc[1] - mrow);
        // store logits for final prob output
        {
            const int n = tile * 64 + w * 8 + (lane & 3) * 2;
            float2 sv; sv.x = sacc[0]; sv.y = sacc[1];
            *(float2*)&S[r0 * S_STRIDE + n] = sv;
        }
        // store E bf16 hi/lo (swizzled, chunk = w)
        {
            const uint32_t eoff = (uint32_t)(r0 * 128 + ((w ^ (r0 & 7)) << 4) + (lane & 3) * 4);
            split_pair(e0, e1, (__nv_bfloat16*)(smem + AS_EH + eoff), (__nv_bfloat16*)(smem + AS_EL + eoff));
        }
        float q = e0 + e1;
        q += __shfl_xor_sync(0xffffffffu, q, 1);
        q += __shfl_xor_sync(0xffffffffu, q, 2);
        if ((lane & 3) == 0) esum[r0 * 8 + w] = q;
        // rescale evidence accumulators
        const float fr = fred[r0];
        #pragma unroll
        for (int nf = 0; nf < 4; nf++) { eacc[nf][0] *= fr; eacc[nf][1] *= fr; }
        __syncthreads();
        if (tid < 8) {
            float ssum = 0.0f;
            #pragma unroll
            for (int ww = 0; ww < 8; ww++) ssum += esum[tid * 8 + ww];
            sred[tid] = sred[tid] * fred[tid] + ssum;
        }

        // ---- evidence mma for this tile ----
        #pragma unroll
        for (int ksl = 0; ksl < 4; ksl++) {
            const int arow = ((lane >> 3) & 1) * 8 + (lane & 7);
            const int ach = ksl * 2 + (lane >> 4);
            const uint32_t aoff = (uint32_t)(arow * 128 + ((ach ^ (arow & 7)) << 4));
            uint32_t ah[4], al[4];
            ldm_x4(ah, sb + AS_EH + aoff);
            ldm_x4(al, sb + AS_EL + aoff);
            #pragma unroll
            for (int g = 0; g < 2; g++) {
                const int brow = ksl * 16 + ((lane >> 3) & 1) * 8 + (lane & 7);
                const int bch = w * 4 + g * 2 + (lane >> 4);
                const uint32_t boff = (uint32_t)(brow * 512 + ((bch ^ (brow & 7)) << 4));
                uint32_t th[4], tl[4];
                ldm_x4t(th, vbase + boff);
                ldm_x4t(tl, vbase + 32768 + boff);
                uint32_t bh0[2] = {th[0], th[1]}, bh1[2] = {th[2], th[3]};
                uint32_t bl0[2] = {tl[0], tl[1]}, bl1[2] = {tl[2], tl[3]};
                mma16816(eacc[g * 2],     ah, bh0);
                mma16816(eacc[g * 2],     ah, bl0);
                mma16816(eacc[g * 2],     al, bh0);
                mma16816(eacc[g * 2 + 1], ah, bh1);
                mma16816(eacc[g * 2 + 1], ah, bl1);
                mma16816(eacc[g * 2 + 1], al, bh1);
            }
        }
        __syncthreads();   // protect E before next tile overwrites
    }

    // ---- final: probs + entropy (warp w owns row w) ----
    {
        const float m_w = mred[w];
        const float inv_w = 1.0f / sred[w];
        const float* Srow = S + w * S_STRIDE;
        float ent = 0.0f;
        float* outA = out + ATT_OFF + (size_t)(row0 + w) * N_;
        #pragma unroll
        for (int j = 0; j < 8; j++) {
            float4 v = *(const float4*)&Srow[lane * 4 + 128 * j];
            float4 p;
            p.x = expf(v.x - m_w) * inv_w;
            p.y = expf(v.y - m_w) * inv_w;
            p.z = expf(v.z - m_w) * inv_w;
            p.w = expf(v.w - m_w) * inv_w;
            *(float4*)&outA[lane * 4 + 128 * j] = p;
            ent += p.x * logf(fmaxf(p.x, 1e-8f));
            ent += p.y * logf(fmaxf(p.y, 1e-8f));
            ent += p.z * logf(fmaxf(p.z, 1e-8f));
            ent += p.w * logf(fmaxf(p.w, 1e-8f));
        }
        ent = warp_sum(ent);
        if (lane == 0) ((float*)(smem + RED_RE))[w] = ent;
    }

    // ---- evidence epilogue ----
    {
        const int grow = row0 + r0;
        const float inv = 1.0f / sred[r0];
        const float lab = labels[grow];
        float lp = 0.0f, lsum = 0.0f;
        #pragma unroll
        for (int nf = 0; nf < 4; nf++) {
            const int d = w * 32 + nf * 8 + (lane & 3) * 2;
            const float e0 = eacc[nf][0] * inv;
            const float e1 = eacc[nf][1] * inv;
            float2 ev2; ev2.x = e0; ev2.y = e1;
            *(float2*)&out[EV_OFF + (size_t)grow * D_ + d] = ev2;
            lp += e0 * Wc[d] + e1 * Wc[d + 1];
            const float2 ph = *(const float2*)&g_phrase[(size_t)grow * D_ + d];
            const float d0 = e0 - lab * ph.x;
            const float d1 = e1 - lab * ph.y;
            lsum += d0 * d0 + d1 * d1;
        }
        lp += __shfl_xor_sync(0xffffffffu, lp, 1);
        lp += __shfl_xor_sync(0xffffffffu, lp, 2);
        if ((lane & 3) == 0) ((float*)(smem + RED_RLOG))[w * 8 + r0] = lp;
        lsum = warp_sum(lsum);
        if (lane == 0) ((float*)(smem + RED_RL))[w] = lsum;
    }
    __syncthreads();

    if (tid < 8) {
        float s = 0.0f;
        #pragma unroll
        for (int ww = 0; ww < 8; ww++) s += ((float*)(smem + RED_RLOG))[ww * 8 + tid];
        out[LOG_OFF + row0 + tid] = s + bcp[0];
    }
    if (tid == 0) {
        float s = 0.0f, e = 0.0f;
        #pragma unroll
        for (int i = 0; i < 8; i++) {
            s += ((float*)(smem + RED_RL))[i];
            e += ((float*)(smem + RED_RE))[i];
        }
        atomicAdd(&g_accum[0], s);
        atomicAdd(&g_accum[1], e);
    }
}

__global__ void k_finalize(float* __restrict__ out) {
    const float proto_loss = g_accum[0] / (float)(B_ * O_ * D_);
    const float sparse_loss = -g_accum[1] / (float)(B_ * O_);
    out[LOSS_OFF] = proto_loss + 0.01f * sparse_loss;
}

// ---------------- launch ----------------
extern "C" void kernel_launch(void* const* d_in, const int* in_sizes, int n_in,
                              void* d_out, int out_size)
{
    (void)in_sizes; (void)n_in; (void)out_size;
    const float* visual_tokens = (const float*)d_in[0];
    const float* phrase_states = (const float*)d_in[1];
    const float* labels        = (const float*)d_in[2];
    const float* Wv            = (const float*)d_in[3];
    const float* bv            = (const float*)d_in[4];
    const float* Wp            = (const float*)d_in[5];
    const float* bp            = (const float*)d_in[6];
    const float* proto         = (const float*)d_in[7];
    const float* Wc            = (const float*)d_in[8];
    const float* bc            = (const float*)d_in[9];
    float* out = (float*)d_out;

    cudaFuncSetAttribute(k_gemm_mma, cudaFuncAttributeMaxDynamicSharedMemorySize, GEMM_SMEM);
    cudaFuncSetAttribute(k_attn_mma, cudaFuncAttributeMaxDynamicSharedMemorySize, ATT_SMEM);

    k_zero<<<1, 1>>>();
    k_split_w<<<512, 256>>>(Wv, Wp);
    k_gemm_mma<<<MV / 64 + MP / 64, 256, GEMM_SMEM>>>(visual_tokens, phrase_states, bv, bp, proto);
    k_attn_mma<<<dim3(8, B_), 256, ATT_SMEM>>>(labels, Wc, bc, out);
    k_finalize<<<1, 1>>>(out);
}

// round 14
// speedup vs baseline: 2.4968x; 1.0108x over previous
#include <cuda_runtime.h>
#include <cuda_bf16.h>
#include <cstdint>

#define B_  16
#define N_  1024
#define O_  64
#define H_  1024
#define D_  256

#define MV  (B_ * N_)      // 16384
#define MP  (B_ * O_)      // 1024

#define LOG_OFF  0
#define ATT_OFF  (B_ * O_)
#define EV_OFF   (ATT_OFF + B_ * O_ * N_)
#define LOSS_OFF (EV_OFF + B_ * O_ * D_)

// ---------------- device scratch ----------------
__device__ float g_phrase[MP * D_];   // normalized phrase fp32 (for loss)
__device__ float g_accum[2];
__device__ float g_evpart[2 * MP * D_];   // split-KV evidence partials
__device__ float g_ms[2 * MP * 2];        // split-KV (m, s) per half per row

__device__ __align__(16) __nv_bfloat16 g_wv_hi[H_ * D_];
__device__ __align__(16) __nv_bfloat16 g_wv_lo[H_ * D_];
__device__ __align__(16) __nv_bfloat16 g_wp_hi[H_ * D_];
__device__ __align__(16) __nv_bfloat16 g_wp_lo[H_ * D_];

__device__ __align__(16) __nv_bfloat16 g_vis_hi[MV * D_];
__device__ __align__(16) __nv_bfloat16 g_vis_lo[MV * D_];
__device__ __align__(16) __nv_bfloat16 g_proto_hi[MP * D_];
__device__ __align__(16) __nv_bfloat16 g_proto_lo[MP * D_];

__global__ void k_zero() { g_accum[0] = 0.0f; g_accum[1] = 0.0f; }

// ---------------- helpers ----------------
__device__ __forceinline__ uint32_t smem_u32(const void* p) {
    uint32_t a;
    asm("{ .reg .u64 t; cvta.to.shared.u64 t, %1; cvt.u32.u64 %0, t; }" : "=r"(a) : "l"(p));
    return a;
}
__device__ __forceinline__ void cpa16(uint32_t s, const void* g) {
    asm volatile("cp.async.cg.shared.global [%0], [%1], 16;" :: "r"(s), "l"(g));
}
#define CP_COMMIT() asm volatile("cp.async.commit_group;" ::: "memory")
#define CP_WAIT1()  asm volatile("cp.async.wait_group 1;" ::: "memory")
#define CP_WAIT0()  asm volatile("cp.async.wait_group 0;" ::: "memory")

__device__ __forceinline__ void ldm_x4(uint32_t* r, uint32_t a) {
    asm volatile("ldmatrix.sync.aligned.m8n8.x4.shared.b16 {%0,%1,%2,%3}, [%4];"
        : "=r"(r[0]), "=r"(r[1]), "=r"(r[2]), "=r"(r[3]) : "r"(a));
}
__device__ __forceinline__ void ldm_x2(uint32_t* r, uint32_t a) {
    asm volatile("ldmatrix.sync.aligned.m8n8.x2.shared.b16 {%0,%1}, [%2];"
        : "=r"(r[0]), "=r"(r[1]) : "r"(a));
}
__device__ __forceinline__ void ldm_x4t(uint32_t* r, uint32_t a) {
    asm volatile("ldmatrix.sync.aligned.m8n8.x4.trans.shared.b16 {%0,%1,%2,%3}, [%4];"
        : "=r"(r[0]), "=r"(r[1]), "=r"(r[2]), "=r"(r[3]) : "r"(a));
}
__device__ __forceinline__ void mma16816(float* c, const uint32_t* a, const uint32_t* b) {
    asm volatile(
        "mma.sync.aligned.m16n8k16.row.col.f32.bf16.bf16.f32 "
        "{%0,%1,%2,%3}, {%4,%5,%6,%7}, {%8,%9}, {%0,%1,%2,%3};"
        : "+f"(c[0]), "+f"(c[1]), "+f"(c[2]), "+f"(c[3])
        : "r"(a[0]), "r"(a[1]), "r"(a[2]), "r"(a[3]), "r"(b[0]), "r"(b[1]));
}

__device__ __forceinline__ float warp_sum(float v) {
    #pragma unroll
    for (int o = 16; o > 0; o >>= 1) v += __shfl_xor_sync(0xffffffffu, v, o);
    return v;
}

__device__ __forceinline__ void split_pair(float x, float y, __nv_bfloat16* hi, __nv_bfloat16* lo) {
    __nv_bfloat162 h, l;
    h.x = __float2bfloat16(x); h.y = __float2bfloat16(y);
    l.x = __float2bfloat16(x - __bfloat162float(h.x));
    l.y = __float2bfloat16(y - __bfloat162float(h.y));
    *(__nv_bfloat162*)hi = h;
    *(__nv_bfloat162*)lo = l;
}

__device__ __forceinline__ uint32_t bf2pack(float a, float b) {
    __nv_bfloat162 h;
    h.x = __float2bfloat16(a); h.y = __float2bfloat16(b);
    return *(uint32_t*)&h;
}

__device__ __forceinline__ void split8(const float4& A, const float4& B, uint4& hi, uint4& lo) {
    hi.x = bf2pack(A.x, A.y); hi.y = bf2pack(A.z, A.w);
    hi.z = bf2pack(B.x, B.y); hi.w = bf2pack(B.z, B.w);
    __nv_bfloat162 h;
    *(uint32_t*)&h = hi.x; lo.x = bf2pack(A.x - __bfloat162float(h.x), A.y - __bfloat162float(h.y));
    *(uint32_t*)&h = hi.y; lo.y = bf2pack(A.z - __bfloat162float(h.x), A.w - __bfloat162float(h.y));
    *(uint32_t*)&h = hi.z; lo.z = bf2pack(B.x - __bfloat162float(h.x), B.y - __bfloat162float(h.y));
    *(uint32_t*)&h = hi.w; lo.w = bf2pack(B.z - __bfloat162float(h.x), B.w - __bfloat162float(h.y));
}

__device__ __forceinline__ void split_one(const float* __restrict__ x,
                                          __nv_bfloat16* __restrict__ hi,
                                          __nv_bfloat16* __restrict__ lo, int i)
{
    float4 v = ((const float4*)x)[i];
    uint4 h, l;
    split8(v, v, h, l);
    ((uint32_t*)hi)[i * 2]     = h.x;
    ((uint32_t*)hi)[i * 2 + 1] = h.y;
    ((uint32_t*)lo)[i * 2]     = l.x;
    ((uint32_t*)lo)[i * 2 + 1] = l.y;
}

__global__ __launch_bounds__(256) void k_split_w(const float* __restrict__ Wv,
                                                 const float* __restrict__ Wp)
{
    const int n4 = H_ * D_ / 4;
    for (int i = blockIdx.x * blockDim.x + threadIdx.x; i < 2 * n4; i += gridDim.x * blockDim.x) {
        if (i < n4) split_one(Wv, g_wv_hi, g_wv_lo, i);
        else        split_one(Wp, g_wp_hi, g_wp_lo, i - n4);
    }
}

// ---------------- mma.sync GEMM, BM=64 BN=256 BK=32, 2 CTA/SM ----------------
#define NSTAGE (H_ / 32)
#define ST_AH 0
#define ST_AL 4096
#define ST_BH 8192
#define ST_BL 24576
#define SMEM_STAGE 40960
#define GEMM_SMEM (2 * SMEM_STAGE)

__global__ __launch_bounds__(256, 2) void k_gemm_mma(const float* __restrict__ visA,
                                                     const float* __restrict__ phrA,
                                                     const float* __restrict__ bv,
                                                     const float* __restrict__ bp,
                                                     const float* __restrict__ proto)
{
    extern __shared__ char smem[];
    const uint32_t sb = smem_u32(smem);
    const int tid = threadIdx.x;
    const int lane = tid & 31;
    const int wid = tid >> 5;
    const int wm = wid & 1;
    const int wn = wid >> 1;

    const bool isV = blockIdx.x < (MV / 64);
    const float* Afp;
    const __nv_bfloat16 *Bh, *Bl;
    const float* bias;
    int m0;
    if (isV) { Afp = visA; Bh = g_wv_hi; Bl = g_wv_lo; bias = bv; m0 = blockIdx.x * 64; }
    else     { Afp = phrA; Bh = g_wp_hi; Bl = g_wp_lo; bias = bp; m0 = (blockIdx.x - MV / 64) * 64; }

    const int a_r = tid >> 2;
    const int a_c = tid & 3;
    const uint32_t a_so = (uint32_t)(a_r * 64 + ((a_c ^ ((a_r >> 1) & 3)) << 4));
    const float* Arow = Afp + (size_t)(m0 + a_r) * H_ + a_c * 8;

    const int b_r = tid >> 3;
    const int b_c = tid & 7;
    uint32_t b_so[4];
    #pragma unroll
    for (int q = 0; q < 4; q++)
        b_so[q] = (uint32_t)(b_r * 512 + (((b_c + q * 8) ^ (b_r & 7)) << 4));

    float acc[2][8][4];
    #pragma unroll
    for (int i = 0; i < 2; i++)
        #pragma unroll
        for (int j = 0; j < 8; j++)
            #pragma unroll
            for (int k = 0; k < 4; k++) acc[i][j][k] = 0.0f;

    float4 fa0 = *(const float4*)(Arow);
    float4 fa1 = *(const float4*)(Arow + 4);
    #pragma unroll
    for (int q = 0; q < 4; q++) {
        cpa16(sb + ST_BH + b_so[q], Bh + (size_t)b_r * D_ + (b_c + q * 8) * 8);
        cpa16(sb + ST_BL + b_so[q], Bl + (size_t)b_r * D_ + (b_c + q * 8) * 8);
    }
    CP_COMMIT();

    for (int s = 0; s < NSTAGE; s++) {
        {
            uint4 h, l;
            split8(fa0, fa1, h, l);
            const uint32_t ast = (uint32_t)((s & 1) * SMEM_STAGE);
            *(uint4*)(smem + ast + ST_AH + a_so) = h;
            *(uint4*)(smem + ast + ST_AL + a_so) = l;
        }
        if (s + 1 < NSTAGE) {
            const int k0 = (s + 1) * 32;
            fa0 = *(const float4*)(Arow + k0);
            fa1 = *(const float4*)(Arow + k0 + 4);
            const uint32_t st = sb + ((s + 1) & 1) * SMEM_STAGE;
            #pragma unroll
            for (int q = 0; q < 4; q++) {
                cpa16(st + ST_BH + b_so[q], Bh + (size_t)(k0 + b_r) * D_ + (b_c + q * 8) * 8);
                cpa16(st + ST_BL + b_so[q], Bl + (size_t)(k0 + b_r) * D_ + (b_c + q * 8) * 8);
            }
        }
        CP_COMMIT();
        CP_WAIT1();
        __syncthreads();

        const uint32_t base = sb + (s & 1) * SMEM_STAGE;

        #pragma unroll
        for (int ks = 0; ks < 2; ks++) {
            uint32_t ahf[2][4], alf[2][4];
            #pragma unroll
            for (int mf = 0; mf < 2; mf++) {
                const int row = wm * 32 + mf * 16 + ((lane >> 3) & 1) * 8 + (lane & 7);
                const int ch  = ks * 2 + (lane >> 4);
                const uint32_t addr = base + ST_AH + (uint32_t)(row * 64 + ((ch ^ ((row >> 1) & 3)) << 4));
                ldm_x4(ahf[mf], addr);
                ldm_x4(alf[mf], addr + (ST_AL - ST_AH));
            }
            #pragma unroll
            for (int g = 0; g < 4; g++) {
                const int row = ks * 16 + ((lane >> 3) & 1) * 8 + (lane & 7);
                const int ch  = wn * 8 + g * 2 + (lane >> 4);
                const uint32_t addr = base + ST_BH + (uint32_t)(row * 512 + ((ch ^ (row & 7)) << 4));
                uint32_t th[4], tl[4];
                ldm_x4t(th, addr);
                ldm_x4t(tl, addr + (ST_BL - ST_BH));
                uint32_t bh0[2] = {th[0], th[1]}, bh1[2] = {th[2], th[3]};
                uint32_t bl0[2] = {tl[0], tl[1]}, bl1[2] = {tl[2], tl[3]};
                #pragma unroll
                for (int mf = 0; mf < 2; mf++) {
                    mma16816(acc[mf][g * 2],     ahf[mf], bh0);
                    mma16816(acc[mf][g * 2],     ahf[mf], bl0);
                    mma16816(acc[mf][g * 2],     alf[mf], bh0);
                    mma16816(acc[mf][g * 2 + 1], ahf[mf], bh1);
                    mma16816(acc[mf][g * 2 + 1], ahf[mf], bl1);
                    mma16816(acc[mf][g * 2 + 1], alf[mf], bh1);
                }
            }
        }
        __syncthreads();
    }

    #pragma unroll
    for (int mf = 0; mf < 2; mf++)
        #pragma unroll
        for (int nf = 0; nf < 8; nf++) {
            const int n = wn * 64 + nf * 8 + (lane & 3) * 2;
            const float bx = bias[n], by = bias[n + 1];
            acc[mf][nf][0] += bx; acc[mf][nf][1] += by;
            acc[mf][nf][2] += bx; acc[mf][nf][3] += by;
        }

    float* part = (float*)smem;
    #pragma unroll
    for (int mf = 0; mf < 2; mf++) {
        float p0 = 0.0f, p1 = 0.0f;
        #pragma unroll
        for (int nf = 0; nf < 8; nf++) {
            p0 = fmaf(acc[mf][nf][0], acc[mf][nf][0], p0);
            p0 = fmaf(acc[mf][nf][1], acc[mf][nf][1], p0);
            p1 = fmaf(acc[mf][nf][2], acc[mf][nf][2], p1);
            p1 = fmaf(acc[mf][nf][3], acc[mf][nf][3], p1);
        }
        p0 += __shfl_xor_sync(0xffffffffu, p0, 1);
        p0 += __shfl_xor_sync(0xffffffffu, p0, 2);
        p1 += __shfl_xor_sync(0xffffffffu, p1, 1);
        p1 += __shfl_xor_sync(0xffffffffu, p1, 2);
        if ((lane & 3) == 0) {
            const int r = wm * 32 + mf * 16 + (lane >> 2);
            part[wn * 64 + r]     = p0;
            part[wn * 64 + r + 8] = p1;
        }
    }
    __syncthreads();

    #pragma unroll
    for (int mf = 0; mf < 2; mf++) {
        const int r0 = wm * 32 + mf * 16 + (lane >> 2);
        const int r1 = r0 + 8;
        const float s0 = part[r0] + part[64 + r0] + part[128 + r0] + part[192 + r0];
        const float s1 = part[r1] + part[64 + r1] + part[128 + r1] + part[192 + r1];
        const float inv0 = 1.0f / fmaxf(sqrtf(s0), 1e-12f);
        const float inv1 = 1.0f / fmaxf(sqrtf(s1), 1e-12f);
        #pragma unroll
        for (int nf = 0; nf < 8; nf++) {
            const int n = wn * 64 + nf * 8 + (lane & 3) * 2;
            acc[mf][nf][0] *= inv0; acc[mf][nf][1] *= inv0;
            acc[mf][nf][2] *= inv1; acc[mf][nf][3] *= inv1;
            if (isV) {
                split_pair(acc[mf][nf][0], acc[mf][nf][1],
                           &g_vis_hi[(size_t)(m0 + r0) * D_ + n], &g_vis_lo[(size_t)(m0 + r0) * D_ + n]);
                split_pair(acc[mf][nf][2], acc[mf][nf][3],
                           &g_vis_hi[(size_t)(m0 + r1) * D_ + n], &g_vis_lo[(size_t)(m0 + r1) * D_ + n]);
            } else {
                float2 w0; w0.x = acc[mf][nf][0]; w0.y = acc[mf][nf][1];
                float2 w1; w1.x = acc[mf][nf][2]; w1.y = acc[mf][nf][3];
                *(float2*)&g_phrase[(size_t)(m0 + r0) * D_ + n] = w0;
                *(float2*)&g_phrase[(size_t)(m0 + r1) * D_ + n] = w1;
            }
        }
    }

    if (!isV) {
        __syncthreads();
        #pragma unroll
        for (int mf = 0; mf < 2; mf++) {
            const int r0l = wm * 32 + mf * 16 + (lane >> 2);
            float p0 = 0.0f, p1 = 0.0f;
            #pragma unroll
            for (int nf = 0; nf < 8; nf++) {
                const int n = wn * 64 + nf * 8 + (lane & 3) * 2;
                const float2 pr0 = *(const float2*)&proto[(size_t)r0l * D_ + n];
                const float2 pr1 = *(const float2*)&proto[(size_t)(r0l + 8) * D_ + n];
                acc[mf][nf][0] += pr0.x; acc[mf][nf][1] += pr0.y;
                acc[mf][nf][2] += pr1.x; acc[mf][nf][3] += pr1.y;
                p0 = fmaf(acc[mf][nf][0], acc[mf][nf][0], p0);
                p0 = fmaf(acc[mf][nf][1], acc[mf][nf][1], p0);
                p1 = fmaf(acc[mf][nf][2], acc[mf][nf][2], p1);
                p1 = fmaf(acc[mf][nf][3], acc[mf][nf][3], p1);
            }
            p0 += __shfl_xor_sync(0xffffffffu, p0, 1);
            p0 += __shfl_xor_sync(0xffffffffu, p0, 2);
            p1 += __shfl_xor_sync(0xffffffffu, p1, 1);
            p1 += __shfl_xor_sync(0xffffffffu, p1, 2);
            if ((lane & 3) == 0) {
                const int r = wm * 32 + mf * 16 + (lane >> 2);
                part[wn * 64 + r]     = p0;
                part[wn * 64 + r + 8] = p1;
            }
        }
        __syncthreads();
        #pragma unroll
        for (int mf = 0; mf < 2; mf++) {
            const int r0 = wm * 32 + mf * 16 + (lane >> 2);
            const int r1 = r0 + 8;
            const float s0 = part[r0] + part[64 + r0] + part[128 + r0] + part[192 + r0];
            const float s1 = part[r1] + part[64 + r1] + part[128 + r1] + part[192 + r1];
            const float inv0 = 1.0f / fmaxf(sqrtf(s0), 1e-12f);
            const float inv1 = 1.0f / fmaxf(sqrtf(s1), 1e-12f);
            #pragma unroll
            for (int nf = 0; nf < 8; nf++) {
                const int n = wn * 64 + nf * 8 + (lane & 3) * 2;
                split_pair(acc[mf][nf][0] * inv0, acc[mf][nf][1] * inv0,
                           &g_proto_hi[(size_t)(m0 + r0) * D_ + n], &g_proto_lo[(size_t)(m0 + r0) * D_ + n]);
                split_pair(acc[mf][nf][2] * inv1, acc[mf][nf][3] * inv1,
                           &g_proto_hi[(size_t)(m0 + r1) * D_ + n], &g_proto_lo[(size_t)(m0 + r1) * D_ + n]);
            }
        }
    }
}

// ---------------- split-KV flash attention (HMMA), 2 CTA/SM ----------------
// block = (og, b, half). 256 threads. Single-buffered 64-token V tiles;
// raw logits -> out ATT (scratch); partial (m, s, unnormalized evidence) -> globals.
#define AS_VH 0
#define AS_VL 32768
#define AS_PH 65536
#define AS_PL 73728
#define AS_EH 81920
#define AS_EL 83968
#define AS_RED 86016
#define RED_M    (AS_RED + 0)
#define RED_S    (AS_RED + 32)
#define RED_F    (AS_RED + 64)
#define RED_WMAX (AS_RED + 96)
#define RED_ESUM (AS_RED + 352)
#define ATT_SMEM (AS_RED + 608)

__global__ __launch_bounds__(256, 2) void k_attn_mma(float* __restrict__ out)
{
    extern __shared__ char smem[];
    const uint32_t sb = smem_u32(smem);
    const int tid = threadIdx.x, lane = tid & 31, w = tid >> 5;
    const int og = blockIdx.x, b = blockIdx.y, half = blockIdx.z;
    const int row0 = b * O_ + og * 8;
    const int t0 = half * (N_ / 2);
    const int r0 = lane >> 2;

    // proto rows
    {
        const int r = tid >> 5, ch = tid & 31;
        const uint32_t off = (uint32_t)(r * 512 + ((ch ^ (r & 7)) << 4));
        const size_t src = (size_t)(row0 + r) * D_ + ch * 8;
        cpa16(sb + AS_PH + off, g_proto_hi + src);
        cpa16(sb + AS_PL + off, g_proto_lo + src);
    }
    CP_COMMIT();

    const __nv_bfloat16* vh = g_vis_hi + ((size_t)(b * N_ + t0)) * D_;
    const __nv_bfloat16* vl = g_vis_lo + ((size_t)(b * N_ + t0)) * D_;
    float* mred = (float*)(smem + RED_M);
    float* sred = (float*)(smem + RED_S);
    float* fred = (float*)(smem + RED_F);
    float* wmax = (float*)(smem + RED_WMAX);
    float* esum = (float*)(smem + RED_ESUM);

    if (tid < 8) { mred[tid] = -1e30f; sred[tid] = 0.0f; }

    float eacc[4][4];
    #pragma unroll
    for (int i = 0; i < 4; i++)
        #pragma unroll
        for (int j = 0; j < 4; j++) eacc[i][j] = 0.0f;

    for (int tile = 0; tile < 8; tile++) {
        // load V tile (single buffer)
        for (int i = tid; i < 2048; i += 256) {
            const int r = i >> 5, ch = i & 31;
            const uint32_t off = (uint32_t)(r * 512 + ((ch ^ (r & 7)) << 4));
            const size_t src = (size_t)(tile * 64 + r) * D_ + ch * 8;
            cpa16(sb + AS_VH + off, vh + src);
            cpa16(sb + AS_VL + off, vl + src);
        }
        CP_COMMIT();
        CP_WAIT0();
        __syncthreads();

        // ---- logits for this tile ----
        float sacc[4] = {0.f, 0.f, 0.f, 0.f};
        #pragma unroll
        for (int ks = 0; ks < 16; ks++) {
            const int arow = ((lane >> 3) & 1) * 8 + (lane & 7);
            const int ach = ks * 2 + (lane >> 4);
            const uint32_t aoff = (uint32_t)(arow * 512 + ((ach ^ (arow & 7)) << 4));
            uint32_t ah[4], al[4];
            ldm_x4(ah, sb + AS_PH + aoff);
            ldm_x4(al, sb + AS_PL + aoff);
            const int brow = w * 8 + (lane & 7);
            const int bch = ks * 2 + ((lane >> 3) & 1);
            const uint32_t boff = (uint32_t)(brow * 512 + ((bch ^ (brow & 7)) << 4));
            uint32_t bh[2], bl[2];
            ldm_x2(bh, sb + AS_VH + boff);
            ldm_x2(bl, sb + AS_VL + boff);
            mma16816(sacc, ah, bh);
            mma16816(sacc, ah, bl);
            mma16816(sacc, al, bh);
        }

        // ---- online softmax bookkeeping ----
        float tmax = fmaxf(sacc[0], sacc[1]);
        tmax = fmaxf(tmax, __shfl_xor_sync(0xffffffffu, tmax, 1));
        tmax = fmaxf(tmax, __shfl_xor_sync(0xffffffffu, tmax, 2));
        if ((lane & 3) == 0) wmax[r0 * 8 + w] = tmax;
        __syncthreads();
        if (tid < 8) {
            float mx = mred[tid];
            #pragma unroll
            for (int ww = 0; ww < 8; ww++) mx = fmaxf(mx, wmax[tid * 8 + ww]);
            fred[tid] = expf(mred[tid] - mx);
            mred[tid] = mx;
        }
        __syncthreads();

        const float mrow = mred[r0];
        const float e0 = expf(sacc[0] - mrow);
        const float e1 = expf(sacc[1] - mrow);
        // raw logits -> gmem scratch (attention region)
        {
            const int n = t0 + tile * 64 + w * 8 + (lane & 3) * 2;
            float2 sv; sv.x = sacc[0]; sv.y = sacc[1];
            *(float2*)&out[ATT_OFF + (size_t)(row0 + r0) * N_ + n] = sv;
        }
        // store E bf16 hi/lo
        {
            const uint32_t eoff = (uint32_t)(r0 * 128 + ((w ^ (r0 & 7)) << 4) + (lane & 3) * 4);
            split_pair(e0, e1, (__nv_bfloat16*)(smem + AS_EH + eoff), (__nv_bfloat16*)(smem + AS_EL + eoff));
        }
        float q = e0 + e1;
        q += __shfl_xor_sync(0xffffffffu, q, 1);
        q += __shfl_xor_sync(0xffffffffu, q, 2);
        if ((lane & 3) == 0) esum[r0 * 8 + w] = q;
        const float fr = fred[r0];
        #pragma unroll
        for (int nf = 0; nf < 4; nf++) { eacc[nf][0] *= fr; eacc[nf][1] *= fr; }
        __syncthreads();
        if (tid < 8) {
            float ssum = 0.0f;
            #pragma unroll
            for (int ww = 0; ww < 8; ww++) ssum += esum[tid * 8 + ww];
            sred[tid] = sred[tid] * fred[tid] + ssum;
        }

        // ---- evidence mma ----
        #pragma unroll
        for (int ksl = 0; ksl < 4; ksl++) {
            const int arow = ((lane >> 3) & 1) * 8 + (lane & 7);
            const int ach = ksl * 2 + (lane >> 4);
            const uint32_t aoff = (uint32_t)(arow * 128 + ((ach ^ (arow & 7)) << 4));
            uint32_t ah[4], al[4];
            ldm_x4(ah, sb + AS_EH + aoff);
            ldm_x4(al, sb + AS_EL + aoff);
            #pragma unroll
            for (int g = 0; g < 2; g++) {
                const int brow = ksl * 16 + ((lane >> 3) & 1) * 8 + (lane & 7);
                const int bch = w * 4 + g * 2 + (lane >> 4);
                const uint32_t boff = (uint32_t)(brow * 512 + ((bch ^ (brow & 7)) << 4));
                uint32_t th[4], tl[4];
                ldm_x4t(th, sb + AS_VH + boff);
                ldm_x4t(tl, sb + AS_VL + boff);
                uint32_t bh0[2] = {th[0], th[1]}, bh1[2] = {th[2], th[3]};
                uint32_t bl0[2] = {tl[0], tl[1]}, bl1[2] = {tl[2], tl[3]};
                mma16816(eacc[g * 2],     ah, bh0);
                mma16816(eacc[g * 2],     ah, bl0);
                mma16816(eacc[g * 2],     al, bh0);
                mma16816(eacc[g * 2 + 1], ah, bh1);
                mma16816(eacc[g * 2 + 1], ah, bl1);
                mma16816(eacc[g * 2 + 1], al, bh1);
            }
        }
        __syncthreads();   // V and E reused next tile
    }

    // ---- write partials ----
    {
        const int grow = row0 + r0;
        #pragma unroll
        for (int nf = 0; nf < 4; nf++) {
            const int d = w * 32 + nf * 8 + (lane & 3) * 2;
            float2 ev2; ev2.x = eacc[nf][0]; ev2.y = eacc[nf][1];
            *(float2*)&g_evpart[((size_t)half * MP + grow) * D_ + d] = ev2;
        }
    }
    if (tid < 8) {
        g_ms[((size_t)half * MP + row0 + tid) * 2]     = mred[tid];
        g_ms[((size_t)half * MP + row0 + tid) * 2 + 1] = sred[tid];
    }
}

// ---------------- combine halves: probs, entropy, evidence, logits, losses ----
__global__ __launch_bounds__(256) void k_attn_fin(
    const float* __restrict__ labels, const float* __restrict__ Wc,
    const float* __restrict__ bcp, float* __restrict__ out)
{
    __shared__ float s_red[8];
    __shared__ float s_red2[8];
    const int row = blockIdx.x;
    const int tid = threadIdx.x, lane = tid & 31, w = tid >> 5;

    const float m0 = g_ms[row * 2],            s0 = g_ms[row * 2 + 1];
    const float m1 = g_ms[(MP + row) * 2],     s1 = g_ms[(MP + row) * 2 + 1];
    const float mstar = fmaxf(m0, m1);
    const float f0 = expf(m0 - mstar), f1 = expf(m1 - mstar);
    const float sstar = s0 * f0 + s1 * f1;
    const float inv = 1.0f / sstar;

    // attention probs + entropy (raw logits currently in out ATT)
    float* att = out + ATT_OFF + (size_t)row * N_;
    float ent = 0.0f;
    {
        float4 v = *(float4*)&att[tid * 4];
        float4 p;
        p.x = expf(v.x - mstar) * inv;
        p.y = expf(v.y - mstar) * inv;
        p.z = expf(v.z - mstar) * inv;
        p.w = expf(v.w - mstar) * inv;
        *(float4*)&att[tid * 4] = p;
        ent += p.x * logf(fmaxf(p.x, 1e-8f));
        ent += p.y * logf(fmaxf(p.y, 1e-8f));
        ent += p.z * logf(fmaxf(p.z, 1e-8f));
        ent += p.w * logf(fmaxf(p.w, 1e-8f));
    }

    // evidence + logits + proto loss (thread tid <-> dim d)
    const int d = tid;
    const float ev = (g_evpart[(size_t)row * D_ + d] * f0
                    + g_evpart[(size_t)(MP + row) * D_ + d] * f1) * inv;
    out[EV_OFF + (size_t)row * D_ + d] = ev;
    float lp = ev * Wc[d];
    const float lab = labels[row];
    const float df = ev - lab * g_phrase[(size_t)row * D_ + d];
    float lsum = df * df;

    ent = warp_sum(ent);
    lp = warp_sum(lp);
    lsum = warp_sum(lsum);
    if (lane == 0) { s_red[w] = lp; s_red2[w] = lsum + ent * 0.0f; }
    __syncthreads();
    // need ent separately: redo with second smem pass
    __shared__ float s_ent[8];
    if (lane == 0) s_ent[w] = ent;
    __syncthreads();
    if (tid == 0) {
        float L = 0.0f, S = 0.0f, E = 0.0f;
        #pragma unroll
        for (int i = 0; i < 8; i++) { L += s_red[i]; S += s_red2[i]; E += s_ent[i]; }
        out[LOG_OFF + row] = L + bcp[0];
        atomicAdd(&g_accum[0], S);
        atomicAdd(&g_accum[1], E);
    }
}

__global__ void k_finalize(float* __restrict__ out) {
    const float proto_loss = g_accum[0] / (float)(B_ * O_ * D_);
    const float sparse_loss = -g_accum[1] / (float)(B_ * O_);
    out[LOSS_OFF] = proto_loss + 0.01f * sparse_loss;
}

// ---------------- launch ----------------
extern "C" void kernel_launch(void* const* d_in, const int* in_sizes, int n_in,
                              void* d_out, int out_size)
{
    (void)in_sizes; (void)n_in; (void)out_size;
    const float* visual_tokens = (const float*)d_in[0];
    const float* phrase_states = (const float*)d_in[1];
    const float* labels        = (const float*)d_in[2];
    const float* Wv            = (const float*)d_in[3];
    const float* bv            = (const float*)d_in[4];
    const float* Wp            = (const float*)d_in[5];
    const float* bp            = (const float*)d_in[6];
    const float* proto         = (const float*)d_in[7];
    const float* Wc            = (const float*)d_in[8];
    const float* bc            = (const float*)d_in[9];
    float* out = (float*)d_out;

    cudaFuncSetAttribute(k_gemm_mma, cudaFuncAttributeMaxDynamicSharedMemorySize, GEMM_SMEM);
    cudaFuncSetAttribute(k_attn_mma, cudaFuncAttributeMaxDynamicSharedMemorySize, ATT_SMEM);

    k_zero<<<1, 1>>>();
    k_split_w<<<512, 256>>>(Wv, Wp);
    k_gemm_mma<<<MV / 64 + MP / 64, 256, GEMM_SMEM>>>(visual_tokens, phrase_states, bv, bp, proto);
    k_attn_mma<<<dim3(8, B_, 2), 256, ATT_SMEM>>>(out);
    k_attn_fin<<<MP, 256>>>(labels, Wc, bc, out);
    k_finalize<<<1, 1>>>(out);
}

// round 15
// speedup vs baseline: 2.7296x; 1.0932x over previous
#include <cuda_runtime.h>
#include <cuda_bf16.h>
#include <cstdint>

#define B_  16
#define N_  1024
#define O_  64
#define H_  1024
#define D_  256

#define MV  (B_ * N_)      // 16384
#define MP  (B_ * O_)      // 1024
#define NQ  4              // token quarters
#define QN  (N_ / NQ)      // 256 tokens per quarter

#define LOG_OFF  0
#define ATT_OFF  (B_ * O_)
#define EV_OFF   (ATT_OFF + B_ * O_ * N_)
#define LOSS_OFF (EV_OFF + B_ * O_ * D_)

// ---------------- device scratch ----------------
__device__ float g_phrase[MP * D_];
__device__ float g_accum[2];
__device__ float g_evpart[NQ * MP * D_];
__device__ float g_ms[NQ * MP * 2];

__device__ __align__(16) __nv_bfloat16 g_wv_hi[H_ * D_];
__device__ __align__(16) __nv_bfloat16 g_wv_lo[H_ * D_];
__device__ __align__(16) __nv_bfloat16 g_wp_hi[H_ * D_];
__device__ __align__(16) __nv_bfloat16 g_wp_lo[H_ * D_];

__device__ __align__(16) __nv_bfloat16 g_vis_hi[MV * D_];
__device__ __align__(16) __nv_bfloat16 g_vis_lo[MV * D_];
__device__ __align__(16) __nv_bfloat16 g_proto_hi[MP * D_];
__device__ __align__(16) __nv_bfloat16 g_proto_lo[MP * D_];

__global__ void k_zero() { g_accum[0] = 0.0f; g_accum[1] = 0.0f; }

// ---------------- helpers ----------------
__device__ __forceinline__ uint32_t smem_u32(const void* p) {
    uint32_t a;
    asm("{ .reg .u64 t; cvta.to.shared.u64 t, %1; cvt.u32.u64 %0, t; }" : "=r"(a) : "l"(p));
    return a;
}
__device__ __forceinline__ void cpa16(uint32_t s, const void* g) {
    asm volatile("cp.async.cg.shared.global [%0], [%1], 16;" :: "r"(s), "l"(g));
}
#define CP_COMMIT() asm volatile("cp.async.commit_group;" ::: "memory")
#define CP_WAIT1()  asm volatile("cp.async.wait_group 1;" ::: "memory")
#define CP_WAIT0()  asm volatile("cp.async.wait_group 0;" ::: "memory")

__device__ __forceinline__ void ldm_x4(uint32_t* r, uint32_t a) {
    asm volatile("ldmatrix.sync.aligned.m8n8.x4.shared.b16 {%0,%1,%2,%3}, [%4];"
        : "=r"(r[0]), "=r"(r[1]), "=r"(r[2]), "=r"(r[3]) : "r"(a));
}
__device__ __forceinline__ void ldm_x2(uint32_t* r, uint32_t a) {
    asm volatile("ldmatrix.sync.aligned.m8n8.x2.shared.b16 {%0,%1}, [%2];"
        : "=r"(r[0]), "=r"(r[1]) : "r"(a));
}
__device__ __forceinline__ void ldm_x4t(uint32_t* r, uint32_t a) {
    asm volatile("ldmatrix.sync.aligned.m8n8.x4.trans.shared.b16 {%0,%1,%2,%3}, [%4];"
        : "=r"(r[0]), "=r"(r[1]), "=r"(r[2]), "=r"(r[3]) : "r"(a));
}
__device__ __forceinline__ void mma16816(float* c, const uint32_t* a, const uint32_t* b) {
    asm volatile(
        "mma.sync.aligned.m16n8k16.row.col.f32.bf16.bf16.f32 "
        "{%0,%1,%2,%3}, {%4,%5,%6,%7}, {%8,%9}, {%0,%1,%2,%3};"
        : "+f"(c[0]), "+f"(c[1]), "+f"(c[2]), "+f"(c[3])
        : "r"(a[0]), "r"(a[1]), "r"(a[2]), "r"(a[3]), "r"(b[0]), "r"(b[1]));
}

__device__ __forceinline__ float warp_sum(float v) {
    #pragma unroll
    for (int o = 16; o > 0; o >>= 1) v += __shfl_xor_sync(0xffffffffu, v, o);
    return v;
}

__device__ __forceinline__ void split_pair(float x, float y, __nv_bfloat16* hi, __nv_bfloat16* lo) {
    __nv_bfloat162 h, l;
    h.x = __float2bfloat16(x); h.y = __float2bfloat16(y);
    l.x = __float2bfloat16(x - __bfloat162float(h.x));
    l.y = __float2bfloat16(y - __bfloat162float(h.y));
    *(__nv_bfloat162*)hi = h;
    *(__nv_bfloat162*)lo = l;
}

__device__ __forceinline__ uint32_t bf2pack(float a, float b) {
    __nv_bfloat162 h;
    h.x = __float2bfloat16(a); h.y = __float2bfloat16(b);
    return *(uint32_t*)&h;
}

__device__ __forceinline__ void split8(const float4& A, const float4& B, uint4& hi, uint4& lo) {
    hi.x = bf2pack(A.x, A.y); hi.y = bf2pack(A.z, A.w);
    hi.z = bf2pack(B.x, B.y); hi.w = bf2pack(B.z, B.w);
    __nv_bfloat162 h;
    *(uint32_t*)&h = hi.x; lo.x = bf2pack(A.x - __bfloat162float(h.x), A.y - __bfloat162float(h.y));
    *(uint32_t*)&h = hi.y; lo.y = bf2pack(A.z - __bfloat162float(h.x), A.w - __bfloat162float(h.y));
    *(uint32_t*)&h = hi.z; lo.z = bf2pack(B.x - __bfloat162float(h.x), B.y - __bfloat162float(h.y));
    *(uint32_t*)&h = hi.w; lo.w = bf2pack(B.z - __bfloat162float(h.x), B.w - __bfloat162float(h.y));
}

__device__ __forceinline__ void split_one(const float* __restrict__ x,
                                          __nv_bfloat16* __restrict__ hi,
                                          __nv_bfloat16* __restrict__ lo, int i)
{
    float4 v = ((const float4*)x)[i];
    uint4 h, l;
    split8(v, v, h, l);
    ((uint32_t*)hi)[i * 2]     = h.x;
    ((uint32_t*)hi)[i * 2 + 1] = h.y;
    ((uint32_t*)lo)[i * 2]     = l.x;
    ((uint32_t*)lo)[i * 2 + 1] = l.y;
}

__global__ __launch_bounds__(256) void k_split_w(const float* __restrict__ Wv,
                                                 const float* __restrict__ Wp)
{
    const int n4 = H_ * D_ / 4;
    for (int i = blockIdx.x * blockDim.x + threadIdx.x; i < 2 * n4; i += gridDim.x * blockDim.x) {
        if (i < n4) split_one(Wv, g_wv_hi, g_wv_lo, i);
        else        split_one(Wp, g_wp_hi, g_wp_lo, i - n4);
    }
}

// ---------------- mma.sync GEMM, BM=64 BN=256 BK=32, 2 CTA/SM ----------------
#define NSTAGE (H_ / 32)
#define ST_AH 0
#define ST_AL 4096
#define ST_BH 8192
#define ST_BL 24576
#define SMEM_STAGE 40960
#define GEMM_SMEM (2 * SMEM_STAGE)

__global__ __launch_bounds__(256, 2) void k_gemm_mma(const float* __restrict__ visA,
                                                     const float* __restrict__ phrA,
                                                     const float* __restrict__ bv,
                                                     const float* __restrict__ bp,
                                                     const float* __restrict__ proto)
{
    extern __shared__ char smem[];
    const uint32_t sb = smem_u32(smem);
    const int tid = threadIdx.x;
    const int lane = tid & 31;
    const int wid = tid >> 5;
    const int wm = wid & 1;
    const int wn = wid >> 1;

    const bool isV = blockIdx.x < (MV / 64);
    const float* Afp;
    const __nv_bfloat16 *Bh, *Bl;
    const float* bias;
    int m0;
    if (isV) { Afp = visA; Bh = g_wv_hi; Bl = g_wv_lo; bias = bv; m0 = blockIdx.x * 64; }
    else     { Afp = phrA; Bh = g_wp_hi; Bl = g_wp_lo; bias = bp; m0 = (blockIdx.x - MV / 64) * 64; }

    const int a_r = tid >> 2;
    const int a_c = tid & 3;
    const uint32_t a_so = (uint32_t)(a_r * 64 + ((a_c ^ ((a_r >> 1) & 3)) << 4));
    const float* Arow = Afp + (size_t)(m0 + a_r) * H_ + a_c * 8;

    const int b_r = tid >> 3;
    const int b_c = tid & 7;
    uint32_t b_so[4];
    #pragma unroll
    for (int q = 0; q < 4; q++)
        b_so[q] = (uint32_t)(b_r * 512 + (((b_c + q * 8) ^ (b_r & 7)) << 4));

    float acc[2][8][4];
    #pragma unroll
    for (int i = 0; i < 2; i++)
        #pragma unroll
        for (int j = 0; j < 8; j++)
            #pragma unroll
            for (int k = 0; k < 4; k++) acc[i][j][k] = 0.0f;

    float4 fa0 = *(const float4*)(Arow);
    float4 fa1 = *(const float4*)(Arow + 4);
    #pragma unroll
    for (int q = 0; q < 4; q++) {
        cpa16(sb + ST_BH + b_so[q], Bh + (size_t)b_r * D_ + (b_c + q * 8) * 8);
        cpa16(sb + ST_BL + b_so[q], Bl + (size_t)b_r * D_ + (b_c + q * 8) * 8);
    }
    CP_COMMIT();

    for (int s = 0; s < NSTAGE; s++) {
        {
            uint4 h, l;
            split8(fa0, fa1, h, l);
            const uint32_t ast = (uint32_t)((s & 1) * SMEM_STAGE);
            *(uint4*)(smem + ast + ST_AH + a_so) = h;
            *(uint4*)(smem + ast + ST_AL + a_so) = l;
        }
        if (s + 1 < NSTAGE) {
            const int k0 = (s + 1) * 32;
            fa0 = *(const float4*)(Arow + k0);
            fa1 = *(const float4*)(Arow + k0 + 4);
            const uint32_t st = sb + ((s + 1) & 1) * SMEM_STAGE;
            #pragma unroll
            for (int q = 0; q < 4; q++) {
                cpa16(st + ST_BH + b_so[q], Bh + (size_t)(k0 + b_r) * D_ + (b_c + q * 8) * 8);
                cpa16(st + ST_BL + b_so[q], Bl + (size_t)(k0 + b_r) * D_ + (b_c + q * 8) * 8);
            }
        }
        CP_COMMIT();
        CP_WAIT1();
        __syncthreads();

        const uint32_t base = sb + (s & 1) * SMEM_STAGE;

        #pragma unroll
        for (int ks = 0; ks < 2; ks++) {
            uint32_t ahf[2][4], alf[2][4];
            #pragma unroll
            for (int mf = 0; mf < 2; mf++) {
                const int row = wm * 32 + mf * 16 + ((lane >> 3) & 1) * 8 + (lane & 7);
                const int ch  = ks * 2 + (lane >> 4);
                const uint32_t addr = base + ST_AH + (uint32_t)(row * 64 + ((ch ^ ((row >> 1) & 3)) << 4));
                ldm_x4(ahf[mf], addr);
                ldm_x4(alf[mf], addr + (ST_AL - ST_AH));
            }
            #pragma unroll
            for (int g = 0; g < 4; g++) {
                const int row = ks * 16 + ((lane >> 3) & 1) * 8 + (lane & 7);
                const int ch  = wn * 8 + g * 2 + (lane >> 4);
                const uint32_t addr = base + ST_BH + (uint32_t)(row * 512 + ((ch ^ (row & 7)) << 4));
                uint32_t th[4], tl[4];
                ldm_x4t(th, addr);
                ldm_x4t(tl, addr + (ST_BL - ST_BH));
                uint32_t bh0[2] = {th[0], th[1]}, bh1[2] = {th[2], th[3]};
                uint32_t bl0[2] = {tl[0], tl[1]}, bl1[2] = {tl[2], tl[3]};
                #pragma unroll
                for (int mf = 0; mf < 2; mf++) {
                    mma16816(acc[mf][g * 2],     ahf[mf], bh0);
                    mma16816(acc[mf][g * 2],     ahf[mf], bl0);
                    mma16816(acc[mf][g * 2],     alf[mf], bh0);
                    mma16816(acc[mf][g * 2 + 1], ahf[mf], bh1);
                    mma16816(acc[mf][g * 2 + 1], ahf[mf], bl1);
                    mma16816(acc[mf][g * 2 + 1], alf[mf], bh1);
                }
            }
        }
        __syncthreads();
    }

    #pragma unroll
    for (int mf = 0; mf < 2; mf++)
        #pragma unroll
        for (int nf = 0; nf < 8; nf++) {
            const int n = wn * 64 + nf * 8 + (lane & 3) * 2;
            const float bx = bias[n], by = bias[n + 1];
            acc[mf][nf][0] += bx; acc[mf][nf][1] += by;
            acc[mf][nf][2] += bx; acc[mf][nf][3] += by;
        }

    float* part = (float*)smem;
    #pragma unroll
    for (int mf = 0; mf < 2; mf++) {
        float p0 = 0.0f, p1 = 0.0f;
        #pragma unroll
        for (int nf = 0; nf < 8; nf++) {
            p0 = fmaf(acc[mf][nf][0], acc[mf][nf][0], p0);
            p0 = fmaf(acc[mf][nf][1], acc[mf][nf][1], p0);
            p1 = fmaf(acc[mf][nf][2], acc[mf][nf][2], p1);
            p1 = fmaf(acc[mf][nf][3], acc[mf][nf][3], p1);
        }
        p0 += __shfl_xor_sync(0xffffffffu, p0, 1);
        p0 += __shfl_xor_sync(0xffffffffu, p0, 2);
        p1 += __shfl_xor_sync(0xffffffffu, p1, 1);
        p1 += __shfl_xor_sync(0xffffffffu, p1, 2);
        if ((lane & 3) == 0) {
            const int r = wm * 32 + mf * 16 + (lane >> 2);
            part[wn * 64 + r]     = p0;
            part[wn * 64 + r + 8] = p1;
        }
    }
    __syncthreads();

    #pragma unroll
    for (int mf = 0; mf < 2; mf++) {
        const int r0 = wm * 32 + mf * 16 + (lane >> 2);
        const int r1 = r0 + 8;
        const float s0 = part[r0] + part[64 + r0] + part[128 + r0] + part[192 + r0];
        const float s1 = part[r1] + part[64 + r1] + part[128 + r1] + part[192 + r1];
        const float inv0 = 1.0f / fmaxf(sqrtf(s0), 1e-12f);
        const float inv1 = 1.0f / fmaxf(sqrtf(s1), 1e-12f);
        #pragma unroll
        for (int nf = 0; nf < 8; nf++) {
            const int n = wn * 64 + nf * 8 + (lane & 3) * 2;
            acc[mf][nf][0] *= inv0; acc[mf][nf][1] *= inv0;
            acc[mf][nf][2] *= inv1; acc[mf][nf][3] *= inv1;
            if (isV) {
                split_pair(acc[mf][nf][0], acc[mf][nf][1],
                           &g_vis_hi[(size_t)(m0 + r0) * D_ + n], &g_vis_lo[(size_t)(m0 + r0) * D_ + n]);
                split_pair(acc[mf][nf][2], acc[mf][nf][3],
                           &g_vis_hi[(size_t)(m0 + r1) * D_ + n], &g_vis_lo[(size_t)(m0 + r1) * D_ + n]);
            } else {
                float2 w0; w0.x = acc[mf][nf][0]; w0.y = acc[mf][nf][1];
                float2 w1; w1.x = acc[mf][nf][2]; w1.y = acc[mf][nf][3];
                *(float2*)&g_phrase[(size_t)(m0 + r0) * D_ + n] = w0;
                *(float2*)&g_phrase[(size_t)(m0 + r1) * D_ + n] = w1;
            }
        }
    }

    if (!isV) {
        __syncthreads();
        #pragma unroll
        for (int mf = 0; mf < 2; mf++) {
            const int r0l = wm * 32 + mf * 16 + (lane >> 2);
            float p0 = 0.0f, p1 = 0.0f;
            #pragma unroll
            for (int nf = 0; nf < 8; nf++) {
                const int n = wn * 64 + nf * 8 + (lane & 3) * 2;
                const float2 pr0 = *(const float2*)&proto[(size_t)r0l * D_ + n];
                const float2 pr1 = *(const float2*)&proto[(size_t)(r0l + 8) * D_ + n];
                acc[mf][nf][0] += pr0.x; acc[mf][nf][1] += pr0.y;
                acc[mf][nf][2] += pr1.x; acc[mf][nf][3] += pr1.y;
                p0 = fmaf(acc[mf][nf][0], acc[mf][nf][0], p0);
                p0 = fmaf(acc[mf][nf][1], acc[mf][nf][1], p0);
                p1 = fmaf(acc[mf][nf][2], acc[mf][nf][2], p1);
                p1 = fmaf(acc[mf][nf][3], acc[mf][nf][3], p1);
            }
            p0 += __shfl_xor_sync(0xffffffffu, p0, 1);
            p0 += __shfl_xor_sync(0xffffffffu, p0, 2);
            p1 += __shfl_xor_sync(0xffffffffu, p1, 1);
            p1 += __shfl_xor_sync(0xffffffffu, p1, 2);
            if ((lane & 3) == 0) {
                const int r = wm * 32 + mf * 16 + (lane >> 2);
                part[wn * 64 + r]     = p0;
                part[wn * 64 + r + 8] = p1;
            }
        }
        __syncthreads();
        #pragma unroll
        for (int mf = 0; mf < 2; mf++) {
            const int r0 = wm * 32 + mf * 16 + (lane >> 2);
            const int r1 = r0 + 8;
            const float s0 = part[r0] + part[64 + r0] + part[128 + r0] + part[192 + r0];
            const float s1 = part[r1] + part[64 + r1] + part[128 + r1] + part[192 + r1];
            const float inv0 = 1.0f / fmaxf(sqrtf(s0), 1e-12f);
            const float inv1 = 1.0f / fmaxf(sqrtf(s1), 1e-12f);
            #pragma unroll
            for (int nf = 0; nf < 8; nf++) {
                const int n = wn * 64 + nf * 8 + (lane & 3) * 2;
                split_pair(acc[mf][nf][0] * inv0, acc[mf][nf][1] * inv0,
                           &g_proto_hi[(size_t)(m0 + r0) * D_ + n], &g_proto_lo[(size_t)(m0 + r0) * D_ + n]);
                split_pair(acc[mf][nf][2] * inv1, acc[mf][nf][3] * inv1,
                           &g_proto_hi[(size_t)(m0 + r1) * D_ + n], &g_proto_lo[(size_t)(m0 + r1) * D_ + n]);
            }
        }
    }
}

// ---------------- split-KV flash attention, 16 o's/CTA, token quarters ------
// block = (og: 16 o's, b, quarter). 256 threads, 2 CTA/SM.
#define AS_VH 0
#define AS_VL 32768
#define AS_PH 65536
#define AS_PL 73728
#define AS_EH 81920
#define AS_EL 84096            // 16 rows x 128B = 2048 (+pad 128)
#define AS_RED 86272
#define RED_M    (AS_RED + 0)      // [16]
#define RED_S    (AS_RED + 64)     // [16]
#define RED_F    (AS_RED + 128)    // [16]
#define RED_WMAX (AS_RED + 192)    // [16][8]
#define RED_ESUM (AS_RED + 704)    // [16][8]
#define ATT_SMEM (AS_RED + 1216)

__global__ __launch_bounds__(256, 2) void k_attn_mma(float* __restrict__ out)
{
    extern __shared__ char smem[];
    const uint32_t sb = smem_u32(smem);
    const int tid = threadIdx.x, lane = tid & 31, w = tid >> 5;
    const int og = blockIdx.x, b = blockIdx.y, qtr = blockIdx.z;
    const int row0 = b * O_ + og * 16;
    const int t0 = qtr * QN;
    const int r0 = lane >> 2;

    // proto: 16 rows
    #pragma unroll
    for (int i = tid; i < 512; i += 256) {
        const int r = i >> 5, ch = i & 31;
        const uint32_t off = (uint32_t)(r * 512 + ((ch ^ (r & 7)) << 4));
        const size_t src = (size_t)(row0 + r) * D_ + ch * 8;
        cpa16(sb + AS_PH + off, g_proto_hi + src);
        cpa16(sb + AS_PL + off, g_proto_lo + src);
    }
    CP_COMMIT();

    const __nv_bfloat16* vh = g_vis_hi + ((size_t)(b * N_ + t0)) * D_;
    const __nv_bfloat16* vl = g_vis_lo + ((size_t)(b * N_ + t0)) * D_;
    float* mred = (float*)(smem + RED_M);
    float* sred = (float*)(smem + RED_S);
    float* fred = (float*)(smem + RED_F);
    float* wmax = (float*)(smem + RED_WMAX);
    float* esum = (float*)(smem + RED_ESUM);

    if (tid < 16) { mred[tid] = -1e30f; sred[tid] = 0.0f; }

    float eacc[4][4];
    #pragma unroll
    for (int i = 0; i < 4; i++)
        #pragma unroll
        for (int j = 0; j < 4; j++) eacc[i][j] = 0.0f;

    for (int tile = 0; tile < QN / 64; tile++) {
        for (int i = tid; i < 2048; i += 256) {
            const int r = i >> 5, ch = i & 31;
            const uint32_t off = (uint32_t)(r * 512 + ((ch ^ (r & 7)) << 4));
            const size_t src = (size_t)(tile * 64 + r) * D_ + ch * 8;
            cpa16(sb + AS_VH + off, vh + src);
            cpa16(sb + AS_VL + off, vl + src);
        }
        CP_COMMIT();
        CP_WAIT0();
        __syncthreads();

        // ---- logits: A = proto[16], B = visual tokens (warp owns 8) ----
        float sacc[4] = {0.f, 0.f, 0.f, 0.f};
        #pragma unroll
        for (int ks = 0; ks < 16; ks++) {
            const int arow = ((lane >> 3) & 1) * 8 + (lane & 7);
            const int ach = ks * 2 + (lane >> 4);
            const uint32_t aoff = (uint32_t)(arow * 512 + ((ach ^ (arow & 7)) << 4));
            uint32_t ah[4], al[4];
            ldm_x4(ah, sb + AS_PH + aoff);
            ldm_x4(al, sb + AS_PL + aoff);
            const int brow = w * 8 + (lane & 7);
            const int bch = ks * 2 + ((lane >> 3) & 1);
            const uint32_t boff = (uint32_t)(brow * 512 + ((bch ^ (brow & 7)) << 4));
            uint32_t bh[2], bl[2];
            ldm_x2(bh, sb + AS_VH + boff);
            ldm_x2(bl, sb + AS_VL + boff);
            mma16816(sacc, ah, bh);
            mma16816(sacc, ah, bl);
            mma16816(sacc, al, bh);
        }

        // ---- online softmax: rows r0 (c0,c1) and r0+8 (c2,c3) ----
        float t0m = fmaxf(sacc[0], sacc[1]);
        t0m = fmaxf(t0m, __shfl_xor_sync(0xffffffffu, t0m, 1));
        t0m = fmaxf(t0m, __shfl_xor_sync(0xffffffffu, t0m, 2));
        float t1m = fmaxf(sacc[2], sacc[3]);
        t1m = fmaxf(t1m, __shfl_xor_sync(0xffffffffu, t1m, 1));
        t1m = fmaxf(t1m, __shfl_xor_sync(0xffffffffu, t1m, 2));
        if ((lane & 3) == 0) {
            wmax[r0 * 8 + w]       = t0m;
            wmax[(r0 + 8) * 8 + w] = t1m;
        }
        __syncthreads();
        if (tid < 16) {
            float mx = mred[tid];
            #pragma unroll
            for (int ww = 0; ww < 8; ww++) mx = fmaxf(mx, wmax[tid * 8 + ww]);
            fred[tid] = expf(mred[tid] - mx);
            mred[tid] = mx;
        }
        __syncthreads();

        const float m0r = mred[r0];
        const float m1r = mred[r0 + 8];
        const float e0 = expf(sacc[0] - m0r);
        const float e1 = expf(sacc[1] - m0r);
        const float e2 = expf(sacc[2] - m1r);
        const float e3 = expf(sacc[3] - m1r);
        // raw logits -> gmem scratch
        {
            const int n = t0 + tile * 64 + w * 8 + (lane & 3) * 2;
            float2 s0v; s0v.x = sacc[0]; s0v.y = sacc[1];
            float2 s1v; s1v.x = sacc[2]; s1v.y = sacc[3];
            *(float2*)&out[ATT_OFF + (size_t)(row0 + r0) * N_ + n]     = s0v;
            *(float2*)&out[ATT_OFF + (size_t)(row0 + r0 + 8) * N_ + n] = s1v;
        }
        // E store (rows r0, r0+8)
        {
            const uint32_t e0off = (uint32_t)(r0 * 128 + ((w ^ (r0 & 7)) << 4) + (lane & 3) * 4);
            const uint32_t e1off = e0off + 8 * 128;
            split_pair(e0, e1, (__nv_bfloat16*)(smem + AS_EH + e0off), (__nv_bfloat16*)(smem + AS_EL + e0off));
            split_pair(e2, e3, (__nv_bfloat16*)(smem + AS_EH + e1off), (__nv_bfloat16*)(smem + AS_EL + e1off));
        }
        float q0 = e0 + e1;
        q0 += __shfl_xor_sync(0xffffffffu, q0, 1);
        q0 += __shfl_xor_sync(0xffffffffu, q0, 2);
        float q1 = e2 + e3;
        q1 += __shfl_xor_sync(0xffffffffu, q1, 1);
        q1 += __shfl_xor_sync(0xffffffffu, q1, 2);
        if ((lane & 3) == 0) {
            esum[r0 * 8 + w]       = q0;
            esum[(r0 + 8) * 8 + w] = q1;
        }
        const float fr0 = fred[r0];
        const float fr1 = fred[r0 + 8];
        #pragma unroll
        for (int nf = 0; nf < 4; nf++) {
            eacc[nf][0] *= fr0; eacc[nf][1] *= fr0;
            eacc[nf][2] *= fr1; eacc[nf][3] *= fr1;
        }
        __syncthreads();
        if (tid < 16) {
            float ssum = 0.0f;
            #pragma unroll
            for (int ww = 0; ww < 8; ww++) ssum += esum[tid * 8 + ww];
            sred[tid] = sred[tid] * fred[tid] + ssum;
        }

        // ---- evidence: A = E[16,64], B = V (warp owns 32 d) ----
        #pragma unroll
        for (int ksl = 0; ksl < 4; ksl++) {
            const int arow = ((lane >> 3) & 1) * 8 + (lane & 7);
            const int ach = ksl * 2 + (lane >> 4);
            const uint32_t aoff = (uint32_t)(arow * 128 + ((ach ^ (arow & 7)) << 4));
            uint32_t ah[4], al[4];
            ldm_x4(ah, sb + AS_EH + aoff);
            ldm_x4(al, sb + AS_EL + aoff);
            #pragma unroll
            for (int g = 0; g < 2; g++) {
                const int brow = ksl * 16 + ((lane >> 3) & 1) * 8 + (lane & 7);
                const int bch = w * 4 + g * 2 + (lane >> 4);
                const uint32_t boff = (uint32_t)(brow * 512 + ((bch ^ (brow & 7)) << 4));
                uint32_t th[4], tl[4];
                ldm_x4t(th, sb + AS_VH + boff);
                ldm_x4t(tl, sb + AS_VL + boff);
                uint32_t bh0[2] = {th[0], th[1]}, bh1[2] = {th[2], th[3]};
                uint32_t bl0[2] = {tl[0], tl[1]}, bl1[2] = {tl[2], tl[3]};
                mma16816(eacc[g * 2],     ah, bh0);
                mma16816(eacc[g * 2],     ah, bl0);
                mma16816(eacc[g * 2],     al, bh0);
                mma16816(eacc[g * 2 + 1], ah, bh1);
                mma16816(eacc[g * 2 + 1], ah, bl1);
                mma16816(eacc[g * 2 + 1], al, bh1);
            }
        }
        __syncthreads();
    }

    // ---- write partials ----
    {
        const int grow0 = row0 + r0;
        const int grow1 = grow0 + 8;
        #pragma unroll
        for (int nf = 0; nf < 4; nf++) {
            const int d = w * 32 + nf * 8 + (lane & 3) * 2;
            float2 ev0; ev0.x = eacc[nf][0]; ev0.y = eacc[nf][1];
            float2 ev1; ev1.x = eacc[nf][2]; ev1.y = eacc[nf][3];
            *(float2*)&g_evpart[((size_t)qtr * MP + grow0) * D_ + d] = ev0;
            *(float2*)&g_evpart[((size_t)qtr * MP + grow1) * D_ + d] = ev1;
        }
    }
    if (tid < 16) {
        g_ms[((size_t)qtr * MP + row0 + tid) * 2]     = mred[tid];
        g_ms[((size_t)qtr * MP + row0 + tid) * 2 + 1] = sred[tid];
    }
}

// ---------------- combine quarters ----------------
__global__ __launch_bounds__(256) void k_attn_fin(
    const float* __restrict__ labels, const float* __restrict__ Wc,
    const float* __restrict__ bcp, float* __restrict__ out)
{
    __shared__ float s_log[8];
    __shared__ float s_loss[8];
    __shared__ float s_ent[8];
    const int row = blockIdx.x;
    const int tid = threadIdx.x, lane = tid & 31, w = tid >> 5;

    float m[NQ], s[NQ];
    #pragma unroll
    for (int q = 0; q < NQ; q++) {
        m[q] = g_ms[((size_t)q * MP + row) * 2];
        s[q] = g_ms[((size_t)q * MP + row) * 2 + 1];
    }
    float mstar = m[0];
    #pragma unroll
    for (int q = 1; q < NQ; q++) mstar = fmaxf(mstar, m[q]);
    float f[NQ], sstar = 0.0f;
    #pragma unroll
    for (int q = 0; q < NQ; q++) { f[q] = expf(m[q] - mstar); sstar += s[q] * f[q]; }
    const float inv = 1.0f / sstar;

    float* att = out + ATT_OFF + (size_t)row * N_;
    float ent = 0.0f;
    {
        float4 v = *(float4*)&att[tid * 4];
        float4 p;
        p.x = expf(v.x - mstar) * inv;
        p.y = expf(v.y - mstar) * inv;
        p.z = expf(v.z - mstar) * inv;
        p.w = expf(v.w - mstar) * inv;
        *(float4*)&att[tid * 4] = p;
        ent += p.x * logf(fmaxf(p.x, 1e-8f));
        ent += p.y * logf(fmaxf(p.y, 1e-8f));
        ent += p.z * logf(fmaxf(p.z, 1e-8f));
        ent += p.w * logf(fmaxf(p.w, 1e-8f));
    }

    const int d = tid;
    float ev = 0.0f;
    #pragma unroll
    for (int q = 0; q < NQ; q++)
        ev += g_evpart[((size_t)q * MP + row) * D_ + d] * f[q];
    ev *= inv;
    out[EV_OFF + (size_t)row * D_ + d] = ev;
    float lp = ev * Wc[d];
    const float lab = labels[row];
    const float df = ev - lab * g_phrase[(size_t)row * D_ + d];
    float lsum = df * df;

    ent = warp_sum(ent);
    lp = warp_sum(lp);
    lsum = warp_sum(lsum);
    if (lane == 0) { s_log[w] = lp; s_loss[w] = lsum; s_ent[w] = ent; }
    __syncthreads();
    if (tid == 0) {
        float L = 0.0f, S = 0.0f, E = 0.0f;
        #pragma unroll
        for (int i = 0; i < 8; i++) { L += s_log[i]; S += s_loss[i]; E += s_ent[i]; }
        out[LOG_OFF + row] = L + bcp[0];
        atomicAdd(&g_accum[0], S);
        atomicAdd(&g_accum[1], E);
    }
}

__global__ void k_finalize(float* __restrict__ out) {
    const float proto_loss = g_accum[0] / (float)(B_ * O_ * D_);
    const float sparse_loss = -g_accum[1] / (float)(B_ * O_);
    out[LOSS_OFF] = proto_loss + 0.01f * sparse_loss;
}

// ---------------- launch ----------------
extern "C" void kernel_launch(void* const* d_in, const int* in_sizes, int n_in,
                              void* d_out, int out_size)
{
    (void)in_sizes; (void)n_in; (void)out_size;
    const float* visual_tokens = (const float*)d_in[0];
    const float* phrase_states = (const float*)d_in[1];
    const float* labels        = (const float*)d_in[2];
    const float* Wv            = (const float*)d_in[3];
    const float* bv            = (const float*)d_in[4];
    const float* Wp            = (const float*)d_in[5];
    const float* bp            = (const float*)d_in[6];
    const float* proto         = (const float*)d_in[7];
    const float* Wc            = (const float*)d_in[8];
    const float* bc            = (const float*)d_in[9];
    float* out = (float*)d_out;

    cudaFuncSetAttribute(k_gemm_mma, cudaFuncAttributeMaxDynamicSharedMemorySize, GEMM_SMEM);
    cudaFuncSetAttribute(k_attn_mma, cudaFuncAttributeMaxDynamicSharedMemorySize, ATT_SMEM);

    k_zero<<<1, 1>>>();
    k_split_w<<<512, 256>>>(Wv, Wp);
    k_gemm_mma<<<MV / 64 + MP / 64, 256, GEMM_SMEM>>>(visual_tokens, phrase_states, bv, bp, proto);
    k_attn_mma<<<dim3(4, B_, NQ), 256, ATT_SMEM>>>(out);
    k_attn_fin<<<MP, 256>>>(labels, Wc, bc, out);
    k_finalize<<<1, 1>>>(out);
}